// round 6
// baseline (speedup 1.0000x reference)
#include <cuda_runtime.h>
#include <cuda_bf16.h>
#include <mma.h>
#include <math.h>
#include <stdint.h>

using namespace nvcuda;

#define NN 50000
#define EE 800000
#define HID 128

// ---------------- scratch (no allocation allowed) ----------------
__device__ float g_buf[(size_t)8 * NN * HID];
__device__ int g_ibuf[NN + (NN + 1) + NN + EE];
// bf16 hi/lo weights for all GEMMs, transposed to [n][k]
#define WTOT 278528
__device__ __align__(16) __nv_bfloat16 g_whi[WTOT];
__device__ __align__(16) __nv_bfloat16 g_wlo[WTOT];

__device__ __forceinline__ float gelu_tanh(float x) {
    float x3 = x * x * x;
    float t = tanhf(0.7978845608028654f * (x + 0.044715f * x3));
    return 0.5f * x * (1.0f + t);
}

// ---------------- CSR build ----------------
__global__ void hist_kernel(const int* __restrict__ dst, int* __restrict__ deg, int E) {
    int e = blockIdx.x * blockDim.x + threadIdx.x;
    if (e < E) atomicAdd(&deg[dst[e]], 1);
}

__global__ void scan_kernel(const int* __restrict__ deg, int* __restrict__ row_ptr, int n) {
    __shared__ int wsum[32];
    __shared__ int carry;
    const int lane = threadIdx.x & 31, wid = threadIdx.x >> 5;
    if (threadIdx.x == 0) { carry = 0; row_ptr[0] = 0; }
    __syncthreads();
    for (int base = 0; base < n; base += 1024) {
        int i = base + threadIdx.x;
        int x = (i < n) ? deg[i] : 0;
#pragma unroll
        for (int o = 1; o < 32; o <<= 1) {
            int t = __shfl_up_sync(0xffffffffu, x, o);
            if (lane >= o) x += t;
        }
        if (lane == 31) wsum[wid] = x;
        __syncthreads();
        if (wid == 0) {
            int y = wsum[lane];
#pragma unroll
            for (int o = 1; o < 32; o <<= 1) {
                int t = __shfl_up_sync(0xffffffffu, y, o);
                if (lane >= o) y += t;
            }
            wsum[lane] = y;
        }
        __syncthreads();
        int off = carry + (wid > 0 ? wsum[wid - 1] : 0);
        if (i < n) row_ptr[i + 1] = off + x;
        __syncthreads();
        if (threadIdx.x == 0) carry += wsum[31];
        __syncthreads();
    }
}

__global__ void cursor_kernel(const int* __restrict__ row_ptr, int* __restrict__ cur, int n) {
    int i = blockIdx.x * blockDim.x + threadIdx.x;
    if (i < n) cur[i] = row_ptr[i];
}

__global__ void scatter_kernel(const int* __restrict__ src, const int* __restrict__ dst,
                               int* __restrict__ cur, int* __restrict__ csr_src, int E) {
    int e = blockIdx.x * blockDim.x + threadIdx.x;
    if (e < E) {
        int p = atomicAdd(&cur[dst[e]], 1);
        csr_src[p] = src[e];
    }
}

// ---------------- weight transpose + bf16 split (all GEMMs, one launch) ------
__global__ void wconv_kernel(
    const float* __restrict__ Wi,
    const float* __restrict__ Wsd, const float* __restrict__ Wdd,
    const float* __restrict__ Wsm, const float* __restrict__ Wdm,
    const float* __restrict__ Wsu, const float* __restrict__ Wdu,
    const float* __restrict__ Wf,
    __nv_bfloat16* __restrict__ bhi, __nv_bfloat16* __restrict__ blo)
{
    int idx = blockIdx.x * blockDim.x + threadIdx.x;
    if (idx >= WTOT) return;
    int base, K; const float *S, *D2;
    if (idx < 32768)       { base = 0;      K = 256; S = Wi;           D2 = nullptr; }
    else if (idx < 65536)  { base = 32768;  K = 128; S = Wsd;          D2 = Wdd; }
    else if (idx < 98304)  { base = 65536;  K = 128; S = Wsd + 16384;  D2 = Wdd + 16384; }
    else if (idx < 131072) { base = 98304;  K = 128; S = Wsm;          D2 = Wdm; }
    else if (idx < 196608) { base = 131072; K = 256; S = Wsu;          D2 = Wdu; }
    else if (idx < 262144) { base = 196608; K = 256; S = Wsu + 32768;  D2 = Wdu + 32768; }
    else                   { base = 262144; K = 128; S = Wf;           D2 = nullptr; }
    int local = idx - base;
    int n = local / K, k = local - n * K;
    const float* W = (D2 && n >= 128) ? D2 : S;
    int nc = (D2 && n >= 128) ? n - 128 : n;
    float x = W[(size_t)k * 128 + nc];
    __nv_bfloat16 h = __float2bfloat16_rn(x);
    bhi[idx] = h;
    blo[idx] = __float2bfloat16_rn(x - __bfloat162float(h));
}

// ---------------- wmma bf16-split GEMM ----------------
// C = A[M,K] @ W[K,128] + bias (opt gelu). A = [A1|A2] K-concat (stride 128).
// W given transposed+split: Bhi/Blo [n][k]; blockIdx.y picks output half.
// Split product: D ≈ Ahi*Whi + Ahi*Wlo + Alo*Whi (fp32 accum).
#define BKC 32

__global__ __launch_bounds__(256) void tgemm_kernel(
    const float* __restrict__ A1, const float* __restrict__ A2,
    const __nv_bfloat16* __restrict__ BhiBase, const __nv_bfloat16* __restrict__ BloBase,
    const float* __restrict__ biasA, const float* __restrict__ biasB,
    float* __restrict__ Ca, float* __restrict__ Cb,
    int M, int K, int act)
{
    __shared__ __nv_bfloat16 sAhi[128 * BKC];
    __shared__ __nv_bfloat16 sAlo[128 * BKC];
    __shared__ __nv_bfloat16 sBhi[128 * BKC];
    __shared__ __nv_bfloat16 sBlo[128 * BKC];
    __shared__ float sEpi[8][256];
    __shared__ float sBias[128];

    const int tid = threadIdx.x;
    const int wid = tid >> 5, lane = tid & 31;
    const int rowBase = blockIdx.x * 128;
    const int yy = blockIdx.y;

    const __nv_bfloat16* Bhi = BhiBase + (size_t)yy * 128 * K;
    const __nv_bfloat16* Blo = BloBase + (size_t)yy * 128 * K;
    const float* bias = yy ? biasB : biasA;
    float* C = yy ? Cb : Ca;

    if (tid < 128) sBias[tid] = bias[tid];

    wmma::fragment<wmma::accumulator, 16, 16, 16, float> acc[8];
#pragma unroll
    for (int t = 0; t < 8; t++) wmma::fill_fragment(acc[t], 0.0f);

    // A loader: thread -> row=tid>>1, 16 consecutive k at (tid&1)*16
    const int ar = tid >> 1, aks = (tid & 1) << 4;
    const int grow = rowBase + ar;
    // B loader: row n = tid&127, hi for tid<128 else lo
    const int bn = tid & 127;

    const int nCh = K / BKC;
    for (int c = 0; c < nCh; c++) {
        // ---- stage A (fp32 -> bf16 hi/lo) ----
        {
            int kg = c * BKC + aks;
            float v[16];
            if (grow < M) {
                const float* Ap; int kl;
                if (kg < 128) { Ap = A1; kl = kg; } else { Ap = A2; kl = kg - 128; }
                const float4* p = reinterpret_cast<const float4*>(Ap + (size_t)grow * 128 + kl);
#pragma unroll
                for (int i = 0; i < 4; i++) {
                    float4 q = p[i];
                    v[i*4+0] = q.x; v[i*4+1] = q.y; v[i*4+2] = q.z; v[i*4+3] = q.w;
                }
            } else {
#pragma unroll
                for (int i = 0; i < 16; i++) v[i] = 0.0f;
            }
            uint32_t* dh = reinterpret_cast<uint32_t*>(sAhi + ar * BKC + aks);
            uint32_t* dl = reinterpret_cast<uint32_t*>(sAlo + ar * BKC + aks);
#pragma unroll
            for (int j = 0; j < 8; j++) {
                float x0 = v[j*2], x1 = v[j*2+1];
                __nv_bfloat16 h0 = __float2bfloat16_rn(x0);
                __nv_bfloat16 h1 = __float2bfloat16_rn(x1);
                __nv_bfloat16 l0 = __float2bfloat16_rn(x0 - __bfloat162float(h0));
                __nv_bfloat16 l1 = __float2bfloat16_rn(x1 - __bfloat162float(h1));
                dh[j] = (uint32_t)__bfloat16_as_ushort(h0) | ((uint32_t)__bfloat16_as_ushort(h1) << 16);
                dl[j] = (uint32_t)__bfloat16_as_ushort(l0) | ((uint32_t)__bfloat16_as_ushort(l1) << 16);
            }
        }
        // ---- stage B (copy bf16 rows; 32 bf16 = 64 bytes = 4 x uint4) ----
        {
            const __nv_bfloat16* srcp = (tid < 128 ? Bhi : Blo) + (size_t)bn * K + c * BKC;
            __nv_bfloat16* dstp = (tid < 128 ? sBhi : sBlo) + bn * BKC;
            const uint4* s4 = reinterpret_cast<const uint4*>(srcp);
            uint4* d4 = reinterpret_cast<uint4*>(dstp);
            d4[0] = s4[0];
            d4[1] = s4[1];
            d4[2] = s4[2];
            d4[3] = s4[3];
        }
        __syncthreads();

        // ---- compute ----
#pragma unroll
        for (int ks = 0; ks < BKC; ks += 16) {
            wmma::fragment<wmma::matrix_a, 16, 16, 16, __nv_bfloat16, wmma::row_major> ah, al;
            wmma::load_matrix_sync(ah, sAhi + (wid * 16) * BKC + ks, BKC);
            wmma::load_matrix_sync(al, sAlo + (wid * 16) * BKC + ks, BKC);
#pragma unroll
            for (int t = 0; t < 8; t++) {
                wmma::fragment<wmma::matrix_b, 16, 16, 16, __nv_bfloat16, wmma::col_major> bh, bl;
                wmma::load_matrix_sync(bh, sBhi + (t * 16) * BKC + ks, BKC);
                wmma::load_matrix_sync(bl, sBlo + (t * 16) * BKC + ks, BKC);
                wmma::mma_sync(acc[t], ah, bh, acc[t]);
                wmma::mma_sync(acc[t], ah, bl, acc[t]);
                wmma::mma_sync(acc[t], al, bh, acc[t]);
            }
        }
        __syncthreads();
    }

    // ---- epilogue: frag -> smem -> bias(+gelu) -> global ----
#pragma unroll
    for (int t = 0; t < 8; t++) {
        wmma::store_matrix_sync(sEpi[wid], acc[t], 16, wmma::mem_row_major);
        __syncwarp();
#pragma unroll
        for (int i = 0; i < 8; i++) {
            int idx = i * 32 + lane;
            int row = idx >> 4, col = idx & 15;
            int r = rowBase + wid * 16 + row;
            if (r < M) {
                float v = sEpi[wid][idx] + sBias[t * 16 + col];
                if (act) v = gelu_tanh(v);
                C[(size_t)r * 128 + t * 16 + col] = v;
            }
        }
        __syncwarp();
    }
}

// ---------------- GATv2 edge aggregation (warp per dst node) ----------------
__device__ __forceinline__ float edge_logit(float4 f, float4 fdv, float4 attnv) {
    float4 ev;
    ev.x = f.x + fdv.x; ev.x = (ev.x > 0.f) ? ev.x : 0.2f * ev.x;
    ev.y = f.y + fdv.y; ev.y = (ev.y > 0.f) ? ev.y : 0.2f * ev.y;
    ev.z = f.z + fdv.z; ev.z = (ev.z > 0.f) ? ev.z : 0.2f * ev.z;
    ev.w = f.w + fdv.w; ev.w = (ev.w > 0.f) ? ev.w : 0.2f * ev.w;
    return ev.x * attnv.x + ev.y * attnv.y + ev.z * attnv.z + ev.w * attnv.w;
}

__global__ __launch_bounds__(256) void gat_edge_kernel(
    const float* __restrict__ fs, const float* __restrict__ fd,
    const float* __restrict__ attn, const float* __restrict__ bout,
    const int* __restrict__ row_ptr, const int* __restrict__ csr_src,
    float* __restrict__ hout, int n_nodes)
{
    const int warp = (blockIdx.x * blockDim.x + threadIdx.x) >> 5;
    const int lane = threadIdx.x & 31;
    if (warp >= n_nodes) return;

    const int off = lane * 4;
    const int nodeBase = warp * 128;

    const float4 fdv   = *reinterpret_cast<const float4*>(fd + nodeBase + off);
    const float4 attnv = *reinterpret_cast<const float4*>(attn + off);

    float m = -INFINITY, s = 0.0f;
    float4 acc = make_float4(0.f, 0.f, 0.f, 0.f);

    int e = row_ptr[warp];
    const int end = row_ptr[warp + 1];

    for (; e + 2 <= end; e += 2) {
        int s0 = csr_src[e], s1 = csr_src[e + 1];
        float4 f0 = *reinterpret_cast<const float4*>(fs + s0 * 128 + off);
        float4 f1 = *reinterpret_cast<const float4*>(fs + s1 * 128 + off);
        float l0 = edge_logit(f0, fdv, attnv);
        float l1 = edge_logit(f1, fdv, attnv);
        l0 += __shfl_xor_sync(0xffffffffu, l0, 1);
        l1 += __shfl_xor_sync(0xffffffffu, l1, 1);
        l0 += __shfl_xor_sync(0xffffffffu, l0, 2);
        l1 += __shfl_xor_sync(0xffffffffu, l1, 2);
        l0 += __shfl_xor_sync(0xffffffffu, l0, 4);
        l1 += __shfl_xor_sync(0xffffffffu, l1, 4);
        {
            float mn = fmaxf(m, l0);
            float sc = __expf(m - mn);
            float p  = __expf(l0 - mn);
            s = s * sc + p;
            acc.x = acc.x * sc + p * f0.x;
            acc.y = acc.y * sc + p * f0.y;
            acc.z = acc.z * sc + p * f0.z;
            acc.w = acc.w * sc + p * f0.w;
            m = mn;
        }
        {
            float mn = fmaxf(m, l1);
            float sc = __expf(m - mn);
            float p  = __expf(l1 - mn);
            s = s * sc + p;
            acc.x = acc.x * sc + p * f1.x;
            acc.y = acc.y * sc + p * f1.y;
            acc.z = acc.z * sc + p * f1.z;
            acc.w = acc.w * sc + p * f1.w;
            m = mn;
        }
    }
    if (e < end) {
        int s0 = csr_src[e];
        float4 f0 = *reinterpret_cast<const float4*>(fs + s0 * 128 + off);
        float l0 = edge_logit(f0, fdv, attnv);
        l0 += __shfl_xor_sync(0xffffffffu, l0, 1);
        l0 += __shfl_xor_sync(0xffffffffu, l0, 2);
        l0 += __shfl_xor_sync(0xffffffffu, l0, 4);
        float mn = fmaxf(m, l0);
        float sc = __expf(m - mn);
        float p  = __expf(l0 - mn);
        s = s * sc + p;
        acc.x = acc.x * sc + p * f0.x;
        acc.y = acc.y * sc + p * f0.y;
        acc.z = acc.z * sc + p * f0.z;
        acc.w = acc.w * sc + p * f0.w;
        m = mn;
    }

    const float4 bv = *reinterpret_cast<const float4*>(bout + off);
    float inv = 1.0f / (s + 1e-9f);
    float4 o;
    o.x = gelu_tanh(acc.x * inv + bv.x);
    o.y = gelu_tanh(acc.y * inv + bv.y);
    o.z = gelu_tanh(acc.z * inv + bv.z);
    o.w = gelu_tanh(acc.w * inv + bv.w);
    *reinterpret_cast<float4*>(hout + nodeBase + off) = o;
}

// ---------------- launch ----------------
extern "C" void kernel_launch(void* const* d_in, const int* in_sizes, int n_in,
                              void* d_out, int out_size) {
    const float* x_t       = (const float*)d_in[0];
    const float* time_emb  = (const float*)d_in[1];
    const int*   src       = (const int*)d_in[2];
    const int*   dst       = (const int*)d_in[3];
    const float* W_init    = (const float*)d_in[4];
    const float* b_init    = (const float*)d_in[5];
    const float* Wsrc_down = (const float*)d_in[6];
    const float* bsrc_down = (const float*)d_in[7];
    const float* Wdst_down = (const float*)d_in[8];
    const float* bdst_down = (const float*)d_in[9];
    const float* attn_down = (const float*)d_in[10];
    const float* bout_down = (const float*)d_in[11];
    const float* Wsrc_mid  = (const float*)d_in[12];
    const float* bsrc_mid  = (const float*)d_in[13];
    const float* Wdst_mid  = (const float*)d_in[14];
    const float* bdst_mid  = (const float*)d_in[15];
    const float* attn_mid  = (const float*)d_in[16];
    const float* bout_mid  = (const float*)d_in[17];
    const float* Wsrc_up   = (const float*)d_in[18];
    const float* bsrc_up   = (const float*)d_in[19];
    const float* Wdst_up   = (const float*)d_in[20];
    const float* bdst_up   = (const float*)d_in[21];
    const float* attn_up   = (const float*)d_in[22];
    const float* bout_up   = (const float*)d_in[23];
    const float* W_fin     = (const float*)d_in[24];
    const float* b_fin     = (const float*)d_in[25];

    const int Nn = in_sizes[0] / HID;
    const int E  = in_sizes[2];

    void* pf; cudaGetSymbolAddress(&pf, g_buf);
    void* pi; cudaGetSymbolAddress(&pi, g_ibuf);
    void* pwh; cudaGetSymbolAddress(&pwh, g_whi);
    void* pwl; cudaGetSymbolAddress(&pwl, g_wlo);
    float* base = (float*)pf;
    const size_t SL = (size_t)NN * HID;
    float* h0 = base + 0 * SL;
    float* h1 = base + 1 * SL;
    float* h2 = base + 2 * SL;
    float* h3 = base + 3 * SL;
    float* h4 = base + 4 * SL;
    float* h5 = base + 5 * SL;
    float* fs = base + 6 * SL;
    float* fd = base + 7 * SL;
    int* ib = (int*)pi;
    int* deg     = ib;
    int* row_ptr = deg + NN;
    int* cur     = row_ptr + NN + 1;
    int* csr     = cur + NN;
    __nv_bfloat16* whi = (__nv_bfloat16*)pwh;
    __nv_bfloat16* wlo = (__nv_bfloat16*)pwl;

    float* out = (float*)d_out;
    float* hfin = (out_size >= 2 * Nn * HID) ? (out + (size_t)Nn * HID) : h5;

    dim3 tb(256);
    int gE = (E + 255) / 256;
    int gN = (Nn + 255) / 256;
    int gx = (Nn + 127) / 128;
    dim3 g1(gx, 1), g2(gx, 2);
    int gGat = (Nn * 32 + 255) / 256;

    // ---- weight conversion (independent of everything else) ----
    wconv_kernel<<<(WTOT + 255) / 256, tb>>>(W_init, Wsrc_down, Wdst_down,
                                             Wsrc_mid, Wdst_mid, Wsrc_up, Wdst_up, W_fin,
                                             whi, wlo);

    // ---- CSR build ----
    cudaMemsetAsync(deg, 0, sizeof(int) * Nn);
    hist_kernel<<<gE, tb>>>(dst, deg, E);
    scan_kernel<<<1, 1024>>>(deg, row_ptr, Nn);
    cursor_kernel<<<gN, tb>>>(row_ptr, cur, Nn);
    scatter_kernel<<<gE, tb>>>(src, dst, cur, csr, E);

    // offsets into g_whi/g_wlo (elements)
    const int OG_INIT = 0, OG_D0 = 32768, OG_D1 = 65536, OG_MID = 98304,
              OG_U0 = 131072, OG_U1 = 196608, OG_FIN = 262144;

    // ---- init: h0 = gelu([x_t|time_emb] @ W_init + b_init) ----
    tgemm_kernel<<<g1, tb>>>(x_t, time_emb, whi + OG_INIT, wlo + OG_INIT,
                             b_init, nullptr, h0, nullptr, Nn, 256, 1);

    // ---- down 0 ----
    tgemm_kernel<<<g2, tb>>>(h0, nullptr, whi + OG_D0, wlo + OG_D0,
                             bsrc_down, bdst_down, fs, fd, Nn, 128, 0);
    gat_edge_kernel<<<gGat, tb>>>(fs, fd, attn_down, bout_down, row_ptr, csr, h1, Nn);

    // ---- down 1 ----
    tgemm_kernel<<<g2, tb>>>(h1, nullptr, whi + OG_D1, wlo + OG_D1,
                             bsrc_down + HID, bdst_down + HID, fs, fd, Nn, 128, 0);
    gat_edge_kernel<<<gGat, tb>>>(fs, fd, attn_down + HID, bout_down + HID, row_ptr, csr, h2, Nn);

    // ---- mid ----
    tgemm_kernel<<<g2, tb>>>(h2, nullptr, whi + OG_MID, wlo + OG_MID,
                             bsrc_mid, bdst_mid, fs, fd, Nn, 128, 0);
    gat_edge_kernel<<<gGat, tb>>>(fs, fd, attn_mid, bout_mid, row_ptr, csr, h3, Nn);

    // ---- up 0: [h3|h1] ----
    tgemm_kernel<<<g2, tb>>>(h3, h1, whi + OG_U0, wlo + OG_U0,
                             bsrc_up, bdst_up, fs, fd, Nn, 256, 0);
    gat_edge_kernel<<<gGat, tb>>>(fs, fd, attn_up, bout_up, row_ptr, csr, h4, Nn);

    // ---- up 1: [h4|h0] ----
    tgemm_kernel<<<g2, tb>>>(h4, h0, whi + OG_U1, wlo + OG_U1,
                             bsrc_up + HID, bdst_up + HID, fs, fd, Nn, 256, 0);
    gat_edge_kernel<<<gGat, tb>>>(fs, fd, attn_up + HID, bout_up + HID, row_ptr, csr, hfin, Nn);

    // ---- final: out = hfin @ W_fin + b_fin ----
    tgemm_kernel<<<g1, tb>>>(hfin, nullptr, whi + OG_FIN, wlo + OG_FIN,
                             b_fin, nullptr, out, nullptr, Nn, 128, 0);
    if (hfin == h5) {
        cudaMemcpyAsync(out + (size_t)Nn * HID, h5, (size_t)Nn * HID * sizeof(float),
                        cudaMemcpyDeviceToDevice);
    }
}

// round 7
// speedup vs baseline: 1.5266x; 1.5266x over previous
#include <cuda_runtime.h>
#include <cuda_bf16.h>
#include <mma.h>
#include <math.h>
#include <stdint.h>

using namespace nvcuda;

#define NN 50000
#define NPAD 50048
#define EE 800000
#define HID 128

// ---------------- scratch (no allocation allowed) ----------------
__device__ float g_buf[(size_t)8 * NPAD * HID];
__device__ int g_ibuf[NN + (NN + 1) + NN + EE];
#define WTOT 278528
__device__ __align__(16) __nv_bfloat16 g_whi[WTOT];
__device__ __align__(16) __nv_bfloat16 g_wlo[WTOT];

__device__ __forceinline__ float gelu_tanh(float x) {
    float x3 = x * x * x;
    float t = tanhf(0.7978845608028654f * (x + 0.044715f * x3));
    return 0.5f * x * (1.0f + t);
}

__device__ __forceinline__ uint32_t smem_u32(const void* p) {
    uint32_t a;
    asm("{ .reg .u64 t; cvta.to.shared.u64 t, %1; cvt.u32.u64 %0, t; }" : "=r"(a) : "l"(p));
    return a;
}
__device__ __forceinline__ void cp_async16(uint32_t dst, const void* src) {
    asm volatile("cp.async.cg.shared.global [%0], [%1], 16;" :: "r"(dst), "l"(src));
}
#define CP_COMMIT() asm volatile("cp.async.commit_group;" ::: "memory")
#define CP_WAIT0()  asm volatile("cp.async.wait_group 0;" ::: "memory")

// ---------------- CSR build ----------------
__global__ void hist_kernel(const int* __restrict__ dst, int* __restrict__ deg, int E) {
    int e = blockIdx.x * blockDim.x + threadIdx.x;
    if (e < E) atomicAdd(&deg[dst[e]], 1);
}

__global__ void scan_kernel(const int* __restrict__ deg, int* __restrict__ row_ptr, int n) {
    __shared__ int wsum[32];
    __shared__ int carry;
    const int lane = threadIdx.x & 31, wid = threadIdx.x >> 5;
    if (threadIdx.x == 0) { carry = 0; row_ptr[0] = 0; }
    __syncthreads();
    for (int base = 0; base < n; base += 1024) {
        int i = base + threadIdx.x;
        int x = (i < n) ? deg[i] : 0;
#pragma unroll
        for (int o = 1; o < 32; o <<= 1) {
            int t = __shfl_up_sync(0xffffffffu, x, o);
            if (lane >= o) x += t;
        }
        if (lane == 31) wsum[wid] = x;
        __syncthreads();
        if (wid == 0) {
            int y = wsum[lane];
#pragma unroll
            for (int o = 1; o < 32; o <<= 1) {
                int t = __shfl_up_sync(0xffffffffu, y, o);
                if (lane >= o) y += t;
            }
            wsum[lane] = y;
        }
        __syncthreads();
        int off = carry + (wid > 0 ? wsum[wid - 1] : 0);
        if (i < n) row_ptr[i + 1] = off + x;
        __syncthreads();
        if (threadIdx.x == 0) carry += wsum[31];
        __syncthreads();
    }
}

__global__ void cursor_kernel(const int* __restrict__ row_ptr, int* __restrict__ cur, int n) {
    int i = blockIdx.x * blockDim.x + threadIdx.x;
    if (i < n) cur[i] = row_ptr[i];
}

__global__ void scatter_kernel(const int* __restrict__ src, const int* __restrict__ dst,
                               int* __restrict__ cur, int* __restrict__ csr_src, int E) {
    int e = blockIdx.x * blockDim.x + threadIdx.x;
    if (e < E) {
        int p = atomicAdd(&cur[dst[e]], 1);
        csr_src[p] = src[e];
    }
}

// ---------------- weight transpose + bf16 split ----------------
__global__ void wconv_kernel(
    const float* __restrict__ Wi,
    const float* __restrict__ Wsd, const float* __restrict__ Wdd,
    const float* __restrict__ Wsm, const float* __restrict__ Wdm,
    const float* __restrict__ Wsu, const float* __restrict__ Wdu,
    const float* __restrict__ Wf,
    __nv_bfloat16* __restrict__ bhi, __nv_bfloat16* __restrict__ blo)
{
    int idx = blockIdx.x * blockDim.x + threadIdx.x;
    if (idx >= WTOT) return;
    int base, K; const float *S, *D2;
    if (idx < 32768)       { base = 0;      K = 256; S = Wi;           D2 = nullptr; }
    else if (idx < 65536)  { base = 32768;  K = 128; S = Wsd;          D2 = Wdd; }
    else if (idx < 98304)  { base = 65536;  K = 128; S = Wsd + 16384;  D2 = Wdd + 16384; }
    else if (idx < 131072) { base = 98304;  K = 128; S = Wsm;          D2 = Wdm; }
    else if (idx < 196608) { base = 131072; K = 256; S = Wsu;          D2 = Wdu; }
    else if (idx < 262144) { base = 196608; K = 256; S = Wsu + 32768;  D2 = Wdu + 32768; }
    else                   { base = 262144; K = 128; S = Wf;           D2 = nullptr; }
    int local = idx - base;
    int n = local / K, k = local - n * K;
    const float* W = (D2 && n >= 128) ? D2 : S;
    int nc = (D2 && n >= 128) ? n - 128 : n;
    float x = W[(size_t)k * 128 + nc];
    __nv_bfloat16 h = __float2bfloat16_rn(x);
    bhi[idx] = h;
    blo[idx] = __float2bfloat16_rn(x - __bfloat162float(h));
}

// ---------------- wmma bf16-split GEMM, cp.async double-buffered -----------
// Stage layout (bytes, per stage of 40960): sAhi[128][40] @0, sAlo @10240,
// sBhi @20480, sBlo @30720. Rows padded to 40 bf16 (80B) for conflict-free LDSM.
#define STG 40960
#define SAH 0
#define SAL 10240
#define SBH 20480
#define SBL 30720
#define TG_DSM (2 * STG)

__global__ __launch_bounds__(512) void tgemm_kernel(
    const float* __restrict__ A1, const float* __restrict__ A2,
    const __nv_bfloat16* __restrict__ BhiBase, const __nv_bfloat16* __restrict__ BloBase,
    const float* __restrict__ biasA, const float* __restrict__ biasB,
    float* __restrict__ Ca, float* __restrict__ Cb,
    int M, int K, int act)
{
    extern __shared__ char dsm[];
    const uint32_t sb = smem_u32(dsm);
    const int tid = threadIdx.x;
    const int wid = tid >> 5, lane = tid & 31;
    const int stripe = wid >> 1, colh = wid & 1;   // warp tile: rows stripe*16, cols colh*64
    const int rowBase = blockIdx.x * 128;
    const int yy = blockIdx.y;

    const __nv_bfloat16* Bhi = BhiBase + (size_t)yy * 128 * K;
    const __nv_bfloat16* Blo = BloBase + (size_t)yy * 128 * K;
    const float* bias = yy ? biasB : biasA;
    float* C = yy ? Cb : Ca;
    const bool direct = (bias == nullptr);

    __shared__ float sBias[128];
    if (!direct && tid < 128) sBias[tid] = bias[tid];

    wmma::fragment<wmma::accumulator, 16, 16, 16, float> acc[4];
#pragma unroll
    for (int t = 0; t < 4; t++) wmma::fill_fragment(acc[t], 0.0f);

    // A loader: row = tid>>2 (0..127), 8 consecutive k at (tid&3)*8
    const int ar = tid >> 2, ks8 = (tid & 3) << 3;
    const int grow = rowBase + ar;
    // B loader: row = tid>>2, 16B chunk q = tid&3
    const int br = tid >> 2, bq = tid & 3;

    float v[8];
    auto loadA = [&](int c) {
        int kg = (c << 5) + ks8;
        if (grow < M) {
            const float* Ap; int kl;
            if (kg < 128) { Ap = A1; kl = kg; } else { Ap = A2; kl = kg - 128; }
            const float4* p = reinterpret_cast<const float4*>(Ap + (size_t)grow * 128 + kl);
            float4 q0 = p[0], q1 = p[1];
            v[0] = q0.x; v[1] = q0.y; v[2] = q0.z; v[3] = q0.w;
            v[4] = q1.x; v[5] = q1.y; v[6] = q1.z; v[7] = q1.w;
        } else {
#pragma unroll
            for (int i = 0; i < 8; i++) v[i] = 0.0f;
        }
    };
    auto storeA = [&](int st) {
        uint32_t hw[4], lw[4];
#pragma unroll
        for (int j = 0; j < 4; j++) {
            float x0 = v[j * 2], x1 = v[j * 2 + 1];
            __nv_bfloat16 h0 = __float2bfloat16_rn(x0);
            __nv_bfloat16 h1 = __float2bfloat16_rn(x1);
            __nv_bfloat16 l0 = __float2bfloat16_rn(x0 - __bfloat162float(h0));
            __nv_bfloat16 l1 = __float2bfloat16_rn(x1 - __bfloat162float(h1));
            hw[j] = (uint32_t)__bfloat16_as_ushort(h0) | ((uint32_t)__bfloat16_as_ushort(h1) << 16);
            lw[j] = (uint32_t)__bfloat16_as_ushort(l0) | ((uint32_t)__bfloat16_as_ushort(l1) << 16);
        }
        char* basep = dsm + st * STG;
        int off = ar * 80 + ks8 * 2;
        *reinterpret_cast<uint4*>(basep + SAH + off) = make_uint4(hw[0], hw[1], hw[2], hw[3]);
        *reinterpret_cast<uint4*>(basep + SAL + off) = make_uint4(lw[0], lw[1], lw[2], lw[3]);
    };
    auto cpB = [&](int st, int c) {
        const __nv_bfloat16* sh = Bhi + (size_t)br * K + (c << 5) + (bq << 3);
        const __nv_bfloat16* sl = Blo + (size_t)br * K + (c << 5) + (bq << 3);
        uint32_t d = sb + st * STG + br * 80 + (bq << 4);
        cp_async16(d + SBH, sh);
        cp_async16(d + SBL, sl);
    };

    // prologue
    loadA(0);
    cpB(0, 0);
    storeA(0);
    CP_COMMIT();
    CP_WAIT0();
    __syncthreads();

    const int nCh = K >> 5;
    for (int c = 0; c < nCh; c++) {
        const int cur = c & 1;
        const bool more = (c + 1 < nCh);
        if (more) {
            loadA(c + 1);
            cpB(cur ^ 1, c + 1);
            CP_COMMIT();
        }
        const __nv_bfloat16* ah_base = reinterpret_cast<const __nv_bfloat16*>(dsm + cur * STG + SAH);
        const __nv_bfloat16* al_base = reinterpret_cast<const __nv_bfloat16*>(dsm + cur * STG + SAL);
        const __nv_bfloat16* bh_base = reinterpret_cast<const __nv_bfloat16*>(dsm + cur * STG + SBH);
        const __nv_bfloat16* bl_base = reinterpret_cast<const __nv_bfloat16*>(dsm + cur * STG + SBL);
#pragma unroll
        for (int ks = 0; ks < 32; ks += 16) {
            wmma::fragment<wmma::matrix_a, 16, 16, 16, __nv_bfloat16, wmma::row_major> ah, al;
            wmma::load_matrix_sync(ah, ah_base + stripe * 16 * 40 + ks, 40);
            wmma::load_matrix_sync(al, al_base + stripe * 16 * 40 + ks, 40);
#pragma unroll
            for (int t = 0; t < 4; t++) {
                int tg = colh * 4 + t;
                wmma::fragment<wmma::matrix_b, 16, 16, 16, __nv_bfloat16, wmma::col_major> bh, bl;
                wmma::load_matrix_sync(bh, bh_base + tg * 16 * 40 + ks, 40);
                wmma::load_matrix_sync(bl, bl_base + tg * 16 * 40 + ks, 40);
                wmma::mma_sync(acc[t], ah, bh, acc[t]);
                wmma::mma_sync(acc[t], ah, bl, acc[t]);
                wmma::mma_sync(acc[t], al, bh, acc[t]);
            }
        }
        if (more) {
            storeA(cur ^ 1);
            CP_WAIT0();
            __syncthreads();
        }
    }

    if (direct) {
        // padded output slabs: full-tile stores are safe
        float* base_out = C + (size_t)(rowBase + stripe * 16) * 128 + colh * 64;
#pragma unroll
        for (int t = 0; t < 4; t++)
            wmma::store_matrix_sync(base_out + t * 16, acc[t], 128, wmma::mem_row_major);
    } else {
        __syncthreads();   // reuse dsm as epilogue buffer
        float* sE = reinterpret_cast<float*>(dsm) + wid * 256;
#pragma unroll
        for (int t = 0; t < 4; t++) {
            int tg = colh * 4 + t;
            wmma::store_matrix_sync(sE, acc[t], 16, wmma::mem_row_major);
            __syncwarp();
#pragma unroll
            for (int i = 0; i < 8; i++) {
                int idx = i * 32 + lane;
                int row = idx >> 4, col = idx & 15;
                int r = rowBase + stripe * 16 + row;
                if (r < M) {
                    float vv = sE[idx] + sBias[tg * 16 + col];
                    if (act) vv = gelu_tanh(vv);
                    C[(size_t)r * 128 + tg * 16 + col] = vv;
                }
            }
            __syncwarp();
        }
    }
}

// ---------------- GATv2 edge aggregation (warp per dst node) ----------------
// fs/fd are bias-FREE projections; bsrc/bdst folded in here.
__device__ __forceinline__ float edge_logit(float4 f, float4 fdv, float4 attnv) {
    float4 ev;
    ev.x = f.x + fdv.x; ev.x = (ev.x > 0.f) ? ev.x : 0.2f * ev.x;
    ev.y = f.y + fdv.y; ev.y = (ev.y > 0.f) ? ev.y : 0.2f * ev.y;
    ev.z = f.z + fdv.z; ev.z = (ev.z > 0.f) ? ev.z : 0.2f * ev.z;
    ev.w = f.w + fdv.w; ev.w = (ev.w > 0.f) ? ev.w : 0.2f * ev.w;
    return ev.x * attnv.x + ev.y * attnv.y + ev.z * attnv.z + ev.w * attnv.w;
}

__global__ __launch_bounds__(256) void gat_edge_kernel(
    const float* __restrict__ fs, const float* __restrict__ fd,
    const float* __restrict__ attn, const float* __restrict__ bout,
    const float* __restrict__ bsrc, const float* __restrict__ bdst,
    const int* __restrict__ row_ptr, const int* __restrict__ csr_src,
    float* __restrict__ hout, int n_nodes)
{
    const int warp = (blockIdx.x * blockDim.x + threadIdx.x) >> 5;
    const int lane = threadIdx.x & 31;
    if (warp >= n_nodes) return;

    const int off = lane * 4;
    const size_t nodeBase = (size_t)warp * 128;

    const float4 bsv   = *reinterpret_cast<const float4*>(bsrc + off);
    const float4 bdv   = *reinterpret_cast<const float4*>(bdst + off);
    float4 fdv = *reinterpret_cast<const float4*>(fd + nodeBase + off);
    fdv.x += bsv.x + bdv.x; fdv.y += bsv.y + bdv.y;
    fdv.z += bsv.z + bdv.z; fdv.w += bsv.w + bdv.w;
    const float4 attnv = *reinterpret_cast<const float4*>(attn + off);

    float m = -INFINITY, s = 0.0f;
    float4 acc = make_float4(0.f, 0.f, 0.f, 0.f);

    int e = row_ptr[warp];
    const int end = row_ptr[warp + 1];

    for (; e + 2 <= end; e += 2) {
        int s0 = csr_src[e], s1 = csr_src[e + 1];
        float4 f0 = *reinterpret_cast<const float4*>(fs + (size_t)s0 * 128 + off);
        float4 f1 = *reinterpret_cast<const float4*>(fs + (size_t)s1 * 128 + off);
        float l0 = edge_logit(f0, fdv, attnv);
        float l1 = edge_logit(f1, fdv, attnv);
        l0 += __shfl_xor_sync(0xffffffffu, l0, 1);
        l1 += __shfl_xor_sync(0xffffffffu, l1, 1);
        l0 += __shfl_xor_sync(0xffffffffu, l0, 2);
        l1 += __shfl_xor_sync(0xffffffffu, l1, 2);
        l0 += __shfl_xor_sync(0xffffffffu, l0, 4);
        l1 += __shfl_xor_sync(0xffffffffu, l1, 4);
        {
            float mn = fmaxf(m, l0);
            float sc = __expf(m - mn);
            float p  = __expf(l0 - mn);
            s = s * sc + p;
            acc.x = acc.x * sc + p * f0.x;
            acc.y = acc.y * sc + p * f0.y;
            acc.z = acc.z * sc + p * f0.z;
            acc.w = acc.w * sc + p * f0.w;
            m = mn;
        }
        {
            float mn = fmaxf(m, l1);
            float sc = __expf(m - mn);
            float p  = __expf(l1 - mn);
            s = s * sc + p;
            acc.x = acc.x * sc + p * f1.x;
            acc.y = acc.y * sc + p * f1.y;
            acc.z = acc.z * sc + p * f1.z;
            acc.w = acc.w * sc + p * f1.w;
            m = mn;
        }
    }
    if (e < end) {
        int s0 = csr_src[e];
        float4 f0 = *reinterpret_cast<const float4*>(fs + (size_t)s0 * 128 + off);
        float l0 = edge_logit(f0, fdv, attnv);
        l0 += __shfl_xor_sync(0xffffffffu, l0, 1);
        l0 += __shfl_xor_sync(0xffffffffu, l0, 2);
        l0 += __shfl_xor_sync(0xffffffffu, l0, 4);
        float mn = fmaxf(m, l0);
        float sc = __expf(m - mn);
        float p  = __expf(l0 - mn);
        s = s * sc + p;
        acc.x = acc.x * sc + p * f0.x;
        acc.y = acc.y * sc + p * f0.y;
        acc.z = acc.z * sc + p * f0.z;
        acc.w = acc.w * sc + p * f0.w;
        m = mn;
    }

    const float4 bv = *reinterpret_cast<const float4*>(bout + off);
    float inv = 1.0f / (s + 1e-9f);
    float salpha = s * inv;   // == sum(alpha); 0 for zero-degree nodes
    float4 o;
    o.x = gelu_tanh(acc.x * inv + bsv.x * salpha + bv.x);
    o.y = gelu_tanh(acc.y * inv + bsv.y * salpha + bv.y);
    o.z = gelu_tanh(acc.z * inv + bsv.z * salpha + bv.z);
    o.w = gelu_tanh(acc.w * inv + bsv.w * salpha + bv.w);
    *reinterpret_cast<float4*>(hout + nodeBase + off) = o;
}

// ---------------- launch ----------------
extern "C" void kernel_launch(void* const* d_in, const int* in_sizes, int n_in,
                              void* d_out, int out_size) {
    const float* x_t       = (const float*)d_in[0];
    const float* time_emb  = (const float*)d_in[1];
    const int*   src       = (const int*)d_in[2];
    const int*   dst       = (const int*)d_in[3];
    const float* W_init    = (const float*)d_in[4];
    const float* b_init    = (const float*)d_in[5];
    const float* Wsrc_down = (const float*)d_in[6];
    const float* bsrc_down = (const float*)d_in[7];
    const float* Wdst_down = (const float*)d_in[8];
    const float* bdst_down = (const float*)d_in[9];
    const float* attn_down = (const float*)d_in[10];
    const float* bout_down = (const float*)d_in[11];
    const float* Wsrc_mid  = (const float*)d_in[12];
    const float* bsrc_mid  = (const float*)d_in[13];
    const float* Wdst_mid  = (const float*)d_in[14];
    const float* bdst_mid  = (const float*)d_in[15];
    const float* attn_mid  = (const float*)d_in[16];
    const float* bout_mid  = (const float*)d_in[17];
    const float* Wsrc_up   = (const float*)d_in[18];
    const float* bsrc_up   = (const float*)d_in[19];
    const float* Wdst_up   = (const float*)d_in[20];
    const float* bdst_up   = (const float*)d_in[21];
    const float* attn_up   = (const float*)d_in[22];
    const float* bout_up   = (const float*)d_in[23];
    const float* W_fin     = (const float*)d_in[24];
    const float* b_fin     = (const float*)d_in[25];

    const int Nn = in_sizes[0] / HID;
    const int E  = in_sizes[2];

    void* pf; cudaGetSymbolAddress(&pf, g_buf);
    void* pi; cudaGetSymbolAddress(&pi, g_ibuf);
    void* pwh; cudaGetSymbolAddress(&pwh, g_whi);
    void* pwl; cudaGetSymbolAddress(&pwl, g_wlo);
    float* base = (float*)pf;
    const size_t SL = (size_t)NPAD * HID;
    float* h0 = base + 0 * SL;
    float* h1 = base + 1 * SL;
    float* h2 = base + 2 * SL;
    float* h3 = base + 3 * SL;
    float* h4 = base + 4 * SL;
    float* h5 = base + 5 * SL;
    float* fs = base + 6 * SL;
    float* fd = base + 7 * SL;
    int* ib = (int*)pi;
    int* deg     = ib;
    int* row_ptr = deg + NN;
    int* cur     = row_ptr + NN + 1;
    int* csr     = cur + NN;
    __nv_bfloat16* whi = (__nv_bfloat16*)pwh;
    __nv_bfloat16* wlo = (__nv_bfloat16*)pwl;

    float* out = (float*)d_out;
    float* hfin = (out_size >= 2 * Nn * HID) ? (out + (size_t)Nn * HID) : h5;

    cudaFuncSetAttribute(tgemm_kernel, cudaFuncAttributeMaxDynamicSharedMemorySize, TG_DSM);

    dim3 tb(256);
    dim3 tg(512);
    int gE = (E + 255) / 256;
    int gN = (Nn + 255) / 256;
    int gx = (Nn + 127) / 128;
    dim3 g1(gx, 1), g2(gx, 2);
    int gGat = (Nn * 32 + 255) / 256;

    // ---- weight conversion ----
    wconv_kernel<<<(WTOT + 255) / 256, tb>>>(W_init, Wsrc_down, Wdst_down,
                                             Wsrc_mid, Wdst_mid, Wsrc_up, Wdst_up, W_fin,
                                             whi, wlo);

    // ---- CSR build ----
    cudaMemsetAsync(deg, 0, sizeof(int) * Nn);
    hist_kernel<<<gE, tb>>>(dst, deg, E);
    scan_kernel<<<1, 1024>>>(deg, row_ptr, Nn);
    cursor_kernel<<<gN, tb>>>(row_ptr, cur, Nn);
    scatter_kernel<<<gE, tb>>>(src, dst, cur, csr, E);

    const int OG_INIT = 0, OG_D0 = 32768, OG_D1 = 65536, OG_MID = 98304,
              OG_U0 = 131072, OG_U1 = 196608, OG_FIN = 262144;

    // ---- init: h0 = gelu([x_t|time_emb] @ W_init + b_init) ----
    tgemm_kernel<<<g1, tg, TG_DSM>>>(x_t, time_emb, whi + OG_INIT, wlo + OG_INIT,
                                     b_init, nullptr, h0, nullptr, Nn, 256, 1);

    // ---- down 0 ----
    tgemm_kernel<<<g2, tg, TG_DSM>>>(h0, nullptr, whi + OG_D0, wlo + OG_D0,
                                     nullptr, nullptr, fs, fd, Nn, 128, 0);
    gat_edge_kernel<<<gGat, tb>>>(fs, fd, attn_down, bout_down, bsrc_down, bdst_down,
                                  row_ptr, csr, h1, Nn);

    // ---- down 1 ----
    tgemm_kernel<<<g2, tg, TG_DSM>>>(h1, nullptr, whi + OG_D1, wlo + OG_D1,
                                     nullptr, nullptr, fs, fd, Nn, 128, 0);
    gat_edge_kernel<<<gGat, tb>>>(fs, fd, attn_down + HID, bout_down + HID,
                                  bsrc_down + HID, bdst_down + HID, row_ptr, csr, h2, Nn);

    // ---- mid ----
    tgemm_kernel<<<g2, tg, TG_DSM>>>(h2, nullptr, whi + OG_MID, wlo + OG_MID,
                                     nullptr, nullptr, fs, fd, Nn, 128, 0);
    gat_edge_kernel<<<gGat, tb>>>(fs, fd, attn_mid, bout_mid, bsrc_mid, bdst_mid,
                                  row_ptr, csr, h3, Nn);

    // ---- up 0: [h3|h1] ----
    tgemm_kernel<<<g2, tg, TG_DSM>>>(h3, h1, whi + OG_U0, wlo + OG_U0,
                                     nullptr, nullptr, fs, fd, Nn, 256, 0);
    gat_edge_kernel<<<gGat, tb>>>(fs, fd, attn_up, bout_up, bsrc_up, bdst_up,
                                  row_ptr, csr, h4, Nn);

    // ---- up 1: [h4|h0] ----
    tgemm_kernel<<<g2, tg, TG_DSM>>>(h4, h0, whi + OG_U1, wlo + OG_U1,
                                     nullptr, nullptr, fs, fd, Nn, 256, 0);
    gat_edge_kernel<<<gGat, tb>>>(fs, fd, attn_up + HID, bout_up + HID,
                                  bsrc_up + HID, bdst_up + HID, row_ptr, csr, hfin, Nn);

    // ---- final: out = hfin @ W_fin + b_fin ----
    tgemm_kernel<<<g1, tg, TG_DSM>>>(hfin, nullptr, whi + OG_FIN, wlo + OG_FIN,
                                     b_fin, nullptr, out, nullptr, Nn, 128, 0);
    if (hfin == h5) {
        cudaMemcpyAsync(out + (size_t)Nn * HID, h5, (size_t)Nn * HID * sizeof(float),
                        cudaMemcpyDeviceToDevice);
    }
}

// round 8
// speedup vs baseline: 1.6774x; 1.0988x over previous
#include <cuda_runtime.h>
#include <cuda_bf16.h>
#include <mma.h>
#include <math.h>
#include <stdint.h>

using namespace nvcuda;

#define NN 50000
#define NPAD 50048
#define EE 800000
#define HID 128

// ---------------- scratch (no allocation allowed) ----------------
__device__ float g_buf[(size_t)8 * NPAD * HID];
__device__ int g_ibuf[NN + (NN + 1) + NN + EE];
#define WTOT 278528
__device__ __align__(16) __nv_bfloat16 g_whi[WTOT];
__device__ __align__(16) __nv_bfloat16 g_wlo[WTOT];

__device__ __forceinline__ float gelu_tanh(float x) {
    float x3 = x * x * x;
    float t = tanhf(0.7978845608028654f * (x + 0.044715f * x3));
    return 0.5f * x * (1.0f + t);
}

__device__ __forceinline__ uint32_t smem_u32(const void* p) {
    uint32_t a;
    asm("{ .reg .u64 t; cvta.to.shared.u64 t, %1; cvt.u32.u64 %0, t; }" : "=r"(a) : "l"(p));
    return a;
}
__device__ __forceinline__ void cp_async16(uint32_t dst, const void* src) {
    asm volatile("cp.async.cg.shared.global [%0], [%1], 16;" :: "r"(dst), "l"(src));
}
#define CP_COMMIT() asm volatile("cp.async.commit_group;" ::: "memory")
#define CP_WAIT0()  asm volatile("cp.async.wait_group 0;" ::: "memory")

// ---------------- CSR build ----------------
__global__ void hist_kernel(const int* __restrict__ dst, int* __restrict__ deg, int E) {
    int e = blockIdx.x * blockDim.x + threadIdx.x;
    if (e < E) atomicAdd(&deg[dst[e]], 1);
}

// scan + cursor fused: row_ptr[i+1] = incl_scan, cur[i] = row_ptr[i]
__global__ void scan_kernel(const int* __restrict__ deg, int* __restrict__ row_ptr,
                            int* __restrict__ cur, int n) {
    __shared__ int wsum[32];
    __shared__ int carry;
    const int lane = threadIdx.x & 31, wid = threadIdx.x >> 5;
    if (threadIdx.x == 0) { carry = 0; row_ptr[0] = 0; }
    __syncthreads();
    for (int base = 0; base < n; base += 1024) {
        int i = base + threadIdx.x;
        int v = (i < n) ? deg[i] : 0;
        int x = v;
#pragma unroll
        for (int o = 1; o < 32; o <<= 1) {
            int t = __shfl_up_sync(0xffffffffu, x, o);
            if (lane >= o) x += t;
        }
        if (lane == 31) wsum[wid] = x;
        __syncthreads();
        if (wid == 0) {
            int y = wsum[lane];
#pragma unroll
            for (int o = 1; o < 32; o <<= 1) {
                int t = __shfl_up_sync(0xffffffffu, y, o);
                if (lane >= o) y += t;
            }
            wsum[lane] = y;
        }
        __syncthreads();
        int off = carry + (wid > 0 ? wsum[wid - 1] : 0);
        if (i < n) {
            row_ptr[i + 1] = off + x;
            cur[i] = off + x - v;
        }
        __syncthreads();
        if (threadIdx.x == 0) carry += wsum[31];
        __syncthreads();
    }
}

__global__ void scatter_kernel(const int* __restrict__ src, const int* __restrict__ dst,
                               int* __restrict__ cur, int* __restrict__ csr_src, int E) {
    int e = blockIdx.x * blockDim.x + threadIdx.x;
    if (e < E) {
        int p = atomicAdd(&cur[dst[e]], 1);
        csr_src[p] = src[e];
    }
}

// ---------------- weight transpose + bf16 split ----------------
__global__ void wconv_kernel(
    const float* __restrict__ Wi,
    const float* __restrict__ Wsd, const float* __restrict__ Wdd,
    const float* __restrict__ Wsm, const float* __restrict__ Wdm,
    const float* __restrict__ Wsu, const float* __restrict__ Wdu,
    const float* __restrict__ Wf,
    __nv_bfloat16* __restrict__ bhi, __nv_bfloat16* __restrict__ blo)
{
    int idx = blockIdx.x * blockDim.x + threadIdx.x;
    if (idx >= WTOT) return;
    int base, K; const float *S, *D2;
    if (idx < 32768)       { base = 0;      K = 256; S = Wi;           D2 = nullptr; }
    else if (idx < 65536)  { base = 32768;  K = 128; S = Wsd;          D2 = Wdd; }
    else if (idx < 98304)  { base = 65536;  K = 128; S = Wsd + 16384;  D2 = Wdd + 16384; }
    else if (idx < 131072) { base = 98304;  K = 128; S = Wsm;          D2 = Wdm; }
    else if (idx < 196608) { base = 131072; K = 256; S = Wsu;          D2 = Wdu; }
    else if (idx < 262144) { base = 196608; K = 256; S = Wsu + 32768;  D2 = Wdu + 32768; }
    else                   { base = 262144; K = 128; S = Wf;           D2 = nullptr; }
    int local = idx - base;
    int n = local / K, k = local - n * K;
    const float* W = (D2 && n >= 128) ? D2 : S;
    int nc = (D2 && n >= 128) ? n - 128 : n;
    float x = W[(size_t)k * 128 + nc];
    __nv_bfloat16 h = __float2bfloat16_rn(x);
    bhi[idx] = h;
    blo[idx] = __float2bfloat16_rn(x - __bfloat162float(h));
}

// ---------------- wmma bf16-split GEMM, cp.async double-buffered -----------
// NB=1: C[M,128]=A@W+bias (guarded epilogue). NB=2: fused dual output, direct
// full-tile stores into padded slabs (no bias). A converted to hi/lo ONCE.
// Stage layout (bytes): sAhi[128][40] @0, sAlo @10240, sBhi[256][40] @20480,
// sBlo @40960. Rows padded to 40 bf16 (80B) for conflict-free LDSM.
#define STG 61440
#define SAH 0
#define SAL 10240
#define SBH 20480
#define SBL 40960
#define TG_DSM (2 * STG)

template<int NB>
__global__ __launch_bounds__(512) void tgemm_kernel(
    const float* __restrict__ A1, const float* __restrict__ A2,
    const __nv_bfloat16* __restrict__ Bhi, const __nv_bfloat16* __restrict__ Blo,
    const float* __restrict__ bias,
    float* __restrict__ Ca, float* __restrict__ Cb,
    int M, int K, int act)
{
    extern __shared__ char dsm[];
    const uint32_t sb = smem_u32(dsm);
    const int tid = threadIdx.x;
    const int wid = tid >> 5, lane = tid & 31;
    const int stripe = wid >> 1, colh = wid & 1;   // rows stripe*16, cols colh*64 (per half)
    const int rowBase = blockIdx.x * 128;
    const bool direct = (bias == nullptr);

    __shared__ float sBias[128];
    if (!direct && tid < 128) sBias[tid] = bias[tid];

    wmma::fragment<wmma::accumulator, 16, 16, 16, float> acc[4 * NB];
#pragma unroll
    for (int t = 0; t < 4 * NB; t++) wmma::fill_fragment(acc[t], 0.0f);

    // A loader: row = tid>>2 (0..127), 8 consecutive k at (tid&3)*8
    const int ar = tid >> 2, ks8 = (tid & 3) << 3;
    const int grow = rowBase + ar;

    float v[8];
    auto loadA = [&](int c) {
        int kg = (c << 5) + ks8;
        if (grow < M) {
            const float* Ap; int kl;
            if (kg < 128) { Ap = A1; kl = kg; } else { Ap = A2; kl = kg - 128; }
            const float4* p = reinterpret_cast<const float4*>(Ap + (size_t)grow * 128 + kl);
            float4 q0 = p[0], q1 = p[1];
            v[0] = q0.x; v[1] = q0.y; v[2] = q0.z; v[3] = q0.w;
            v[4] = q1.x; v[5] = q1.y; v[6] = q1.z; v[7] = q1.w;
        } else {
#pragma unroll
            for (int i = 0; i < 8; i++) v[i] = 0.0f;
        }
    };
    auto storeA = [&](int st) {
        uint32_t hw[4], lw[4];
#pragma unroll
        for (int j = 0; j < 4; j++) {
            float x0 = v[j * 2], x1 = v[j * 2 + 1];
            __nv_bfloat16 h0 = __float2bfloat16_rn(x0);
            __nv_bfloat16 h1 = __float2bfloat16_rn(x1);
            __nv_bfloat16 l0 = __float2bfloat16_rn(x0 - __bfloat162float(h0));
            __nv_bfloat16 l1 = __float2bfloat16_rn(x1 - __bfloat162float(h1));
            hw[j] = (uint32_t)__bfloat16_as_ushort(h0) | ((uint32_t)__bfloat16_as_ushort(h1) << 16);
            lw[j] = (uint32_t)__bfloat16_as_ushort(l0) | ((uint32_t)__bfloat16_as_ushort(l1) << 16);
        }
        char* basep = dsm + st * STG;
        int off = ar * 80 + ks8 * 2;
        *reinterpret_cast<uint4*>(basep + SAH + off) = make_uint4(hw[0], hw[1], hw[2], hw[3]);
        *reinterpret_cast<uint4*>(basep + SAL + off) = make_uint4(lw[0], lw[1], lw[2], lw[3]);
    };
    auto cpB = [&](int st, int c) {
        if (NB == 2) {
            int r = tid >> 1, q0 = (tid & 1) << 1;
#pragma unroll
            for (int dq = 0; dq < 2; dq++) {
                int q = q0 + dq;
                uint32_t d = sb + st * STG + r * 80 + (q << 4);
                const __nv_bfloat16* gh = Bhi + (size_t)r * K + (c << 5) + (q << 3);
                const __nv_bfloat16* gl = Blo + (size_t)r * K + (c << 5) + (q << 3);
                cp_async16(d + SBH, gh);
                cp_async16(d + SBL, gl);
            }
        } else {
            int r = tid >> 2, q = tid & 3;
            uint32_t d = sb + st * STG + r * 80 + (q << 4);
            cp_async16(d + SBH, Bhi + (size_t)r * K + (c << 5) + (q << 3));
            cp_async16(d + SBL, Blo + (size_t)r * K + (c << 5) + (q << 3));
        }
    };

    // prologue
    loadA(0);
    cpB(0, 0);
    storeA(0);
    CP_COMMIT();
    CP_WAIT0();
    __syncthreads();

    const int nCh = K >> 5;
    for (int c = 0; c < nCh; c++) {
        const int cur = c & 1;
        const bool more = (c + 1 < nCh);
        if (more) {
            loadA(c + 1);
            cpB(cur ^ 1, c + 1);
            CP_COMMIT();
        }
        const __nv_bfloat16* ah_base = reinterpret_cast<const __nv_bfloat16*>(dsm + cur * STG + SAH);
        const __nv_bfloat16* al_base = reinterpret_cast<const __nv_bfloat16*>(dsm + cur * STG + SAL);
        const __nv_bfloat16* bh_base = reinterpret_cast<const __nv_bfloat16*>(dsm + cur * STG + SBH);
        const __nv_bfloat16* bl_base = reinterpret_cast<const __nv_bfloat16*>(dsm + cur * STG + SBL);
#pragma unroll
        for (int ks = 0; ks < 32; ks += 16) {
            wmma::fragment<wmma::matrix_a, 16, 16, 16, __nv_bfloat16, wmma::row_major> ah, al;
            wmma::load_matrix_sync(ah, ah_base + stripe * 16 * 40 + ks, 40);
            wmma::load_matrix_sync(al, al_base + stripe * 16 * 40 + ks, 40);
#pragma unroll
            for (int t = 0; t < 4 * NB; t++) {
                int hb = t >> 2, tc = t & 3;
                int brow = hb * 128 + colh * 64 + tc * 16;
                wmma::fragment<wmma::matrix_b, 16, 16, 16, __nv_bfloat16, wmma::col_major> bh, bl;
                wmma::load_matrix_sync(bh, bh_base + brow * 40 + ks, 40);
                wmma::load_matrix_sync(bl, bl_base + brow * 40 + ks, 40);
                wmma::mma_sync(acc[t], ah, bh, acc[t]);
                wmma::mma_sync(acc[t], ah, bl, acc[t]);
                wmma::mma_sync(acc[t], al, bh, acc[t]);
            }
        }
        if (more) {
            storeA(cur ^ 1);
            CP_WAIT0();
            __syncthreads();
        }
    }

    if (direct) {
        // padded slabs: full-tile stores safe
#pragma unroll
        for (int t = 0; t < 4 * NB; t++) {
            int hb = t >> 2, tc = t & 3;
            float* Cp = hb ? Cb : Ca;
            wmma::store_matrix_sync(
                Cp + (size_t)(rowBase + stripe * 16) * 128 + colh * 64 + tc * 16,
                acc[t], 128, wmma::mem_row_major);
        }
    } else {
        __syncthreads();   // reuse dsm
        float* sE = reinterpret_cast<float*>(dsm) + wid * 256;
#pragma unroll
        for (int t = 0; t < 4 * NB; t++) {
            int tc = t & 3;
            int tg = colh * 4 + tc;
            wmma::store_matrix_sync(sE, acc[t], 16, wmma::mem_row_major);
            __syncwarp();
#pragma unroll
            for (int i = 0; i < 8; i++) {
                int idx = i * 32 + lane;
                int row = idx >> 4, col = idx & 15;
                int r = rowBase + stripe * 16 + row;
                if (r < M) {
                    float vv = sE[idx] + sBias[tg * 16 + col];
                    if (act) vv = gelu_tanh(vv);
                    Ca[(size_t)r * 128 + tg * 16 + col] = vv;
                }
            }
            __syncwarp();
        }
    }
}

// ---------------- GATv2 edge aggregation (warp per dst node) ----------------
// fs/fd bias-free; bsrc/bdst folded here. No max-subtraction: logits are
// bounded (clamped at 80), softmax is shift-invariant.
__device__ __forceinline__ float edge_logit(float4 f, float4 fdv, float4 attnv) {
    float4 ev;
    ev.x = f.x + fdv.x; ev.x = (ev.x > 0.f) ? ev.x : 0.2f * ev.x;
    ev.y = f.y + fdv.y; ev.y = (ev.y > 0.f) ? ev.y : 0.2f * ev.y;
    ev.z = f.z + fdv.z; ev.z = (ev.z > 0.f) ? ev.z : 0.2f * ev.z;
    ev.w = f.w + fdv.w; ev.w = (ev.w > 0.f) ? ev.w : 0.2f * ev.w;
    return ev.x * attnv.x + ev.y * attnv.y + ev.z * attnv.z + ev.w * attnv.w;
}

__global__ __launch_bounds__(256) void gat_edge_kernel(
    const float* __restrict__ fs, const float* __restrict__ fd,
    const float* __restrict__ attn, const float* __restrict__ bout,
    const float* __restrict__ bsrc, const float* __restrict__ bdst,
    const int* __restrict__ row_ptr, const int* __restrict__ csr_src,
    float* __restrict__ hout, int n_nodes)
{
    const int warp = (blockIdx.x * blockDim.x + threadIdx.x) >> 5;
    const int lane = threadIdx.x & 31;
    if (warp >= n_nodes) return;

    const int off = lane * 4;
    const size_t nodeBase = (size_t)warp * 128;

    const float4 bsv = *reinterpret_cast<const float4*>(bsrc + off);
    const float4 bdv = *reinterpret_cast<const float4*>(bdst + off);
    float4 fdv = *reinterpret_cast<const float4*>(fd + nodeBase + off);
    fdv.x += bsv.x + bdv.x; fdv.y += bsv.y + bdv.y;
    fdv.z += bsv.z + bdv.z; fdv.w += bsv.w + bdv.w;
    const float4 attnv = *reinterpret_cast<const float4*>(attn + off);

    float s = 0.0f;
    float4 acc = make_float4(0.f, 0.f, 0.f, 0.f);

    int e = row_ptr[warp];
    const int end = row_ptr[warp + 1];

    for (; e + 4 <= end; e += 4) {
        int i0 = csr_src[e],     i1 = csr_src[e + 1];
        int i2 = csr_src[e + 2], i3 = csr_src[e + 3];
        float4 f0 = *reinterpret_cast<const float4*>(fs + (size_t)i0 * 128 + off);
        float4 f1 = *reinterpret_cast<const float4*>(fs + (size_t)i1 * 128 + off);
        float4 f2 = *reinterpret_cast<const float4*>(fs + (size_t)i2 * 128 + off);
        float4 f3 = *reinterpret_cast<const float4*>(fs + (size_t)i3 * 128 + off);
        float l0 = edge_logit(f0, fdv, attnv);
        float l1 = edge_logit(f1, fdv, attnv);
        float l2 = edge_logit(f2, fdv, attnv);
        float l3 = edge_logit(f3, fdv, attnv);
        l0 += __shfl_xor_sync(0xffffffffu, l0, 1);
        l1 += __shfl_xor_sync(0xffffffffu, l1, 1);
        l2 += __shfl_xor_sync(0xffffffffu, l2, 1);
        l3 += __shfl_xor_sync(0xffffffffu, l3, 1);
        l0 += __shfl_xor_sync(0xffffffffu, l0, 2);
        l1 += __shfl_xor_sync(0xffffffffu, l1, 2);
        l2 += __shfl_xor_sync(0xffffffffu, l2, 2);
        l3 += __shfl_xor_sync(0xffffffffu, l3, 2);
        l0 += __shfl_xor_sync(0xffffffffu, l0, 4);
        l1 += __shfl_xor_sync(0xffffffffu, l1, 4);
        l2 += __shfl_xor_sync(0xffffffffu, l2, 4);
        l3 += __shfl_xor_sync(0xffffffffu, l3, 4);
        float p0 = __expf(fminf(l0, 80.f));
        float p1 = __expf(fminf(l1, 80.f));
        float p2 = __expf(fminf(l2, 80.f));
        float p3 = __expf(fminf(l3, 80.f));
        s += (p0 + p1) + (p2 + p3);
        acc.x = fmaf(p0, f0.x, fmaf(p1, f1.x, fmaf(p2, f2.x, fmaf(p3, f3.x, acc.x))));
        acc.y = fmaf(p0, f0.y, fmaf(p1, f1.y, fmaf(p2, f2.y, fmaf(p3, f3.y, acc.y))));
        acc.z = fmaf(p0, f0.z, fmaf(p1, f1.z, fmaf(p2, f2.z, fmaf(p3, f3.z, acc.z))));
        acc.w = fmaf(p0, f0.w, fmaf(p1, f1.w, fmaf(p2, f2.w, fmaf(p3, f3.w, acc.w))));
    }
    for (; e < end; e++) {
        int i0 = csr_src[e];
        float4 f0 = *reinterpret_cast<const float4*>(fs + (size_t)i0 * 128 + off);
        float l0 = edge_logit(f0, fdv, attnv);
        l0 += __shfl_xor_sync(0xffffffffu, l0, 1);
        l0 += __shfl_xor_sync(0xffffffffu, l0, 2);
        l0 += __shfl_xor_sync(0xffffffffu, l0, 4);
        float p0 = __expf(fminf(l0, 80.f));
        s += p0;
        acc.x = fmaf(p0, f0.x, acc.x);
        acc.y = fmaf(p0, f0.y, acc.y);
        acc.z = fmaf(p0, f0.z, acc.z);
        acc.w = fmaf(p0, f0.w, acc.w);
    }

    const float4 bv = *reinterpret_cast<const float4*>(bout + off);
    float inv = 1.0f / (s + 1e-9f);
    float salpha = s * inv;   // sum(alpha); 0 for zero-degree nodes
    float4 o;
    o.x = gelu_tanh(acc.x * inv + bsv.x * salpha + bv.x);
    o.y = gelu_tanh(acc.y * inv + bsv.y * salpha + bv.y);
    o.z = gelu_tanh(acc.z * inv + bsv.z * salpha + bv.z);
    o.w = gelu_tanh(acc.w * inv + bsv.w * salpha + bv.w);
    *reinterpret_cast<float4*>(hout + nodeBase + off) = o;
}

// ---------------- launch ----------------
extern "C" void kernel_launch(void* const* d_in, const int* in_sizes, int n_in,
                              void* d_out, int out_size) {
    const float* x_t       = (const float*)d_in[0];
    const float* time_emb  = (const float*)d_in[1];
    const int*   src       = (const int*)d_in[2];
    const int*   dst       = (const int*)d_in[3];
    const float* W_init    = (const float*)d_in[4];
    const float* b_init    = (const float*)d_in[5];
    const float* Wsrc_down = (const float*)d_in[6];
    const float* bsrc_down = (const float*)d_in[7];
    const float* Wdst_down = (const float*)d_in[8];
    const float* bdst_down = (const float*)d_in[9];
    const float* attn_down = (const float*)d_in[10];
    const float* bout_down = (const float*)d_in[11];
    const float* Wsrc_mid  = (const float*)d_in[12];
    const float* bsrc_mid  = (const float*)d_in[13];
    const float* Wdst_mid  = (const float*)d_in[14];
    const float* bdst_mid  = (const float*)d_in[15];
    const float* attn_mid  = (const float*)d_in[16];
    const float* bout_mid  = (const float*)d_in[17];
    const float* Wsrc_up   = (const float*)d_in[18];
    const float* bsrc_up   = (const float*)d_in[19];
    const float* Wdst_up   = (const float*)d_in[20];
    const float* bdst_up   = (const float*)d_in[21];
    const float* attn_up   = (const float*)d_in[22];
    const float* bout_up   = (const float*)d_in[23];
    const float* W_fin     = (const float*)d_in[24];
    const float* b_fin     = (const float*)d_in[25];

    const int Nn = in_sizes[0] / HID;
    const int E  = in_sizes[2];

    void* pf; cudaGetSymbolAddress(&pf, g_buf);
    void* pi; cudaGetSymbolAddress(&pi, g_ibuf);
    void* pwh; cudaGetSymbolAddress(&pwh, g_whi);
    void* pwl; cudaGetSymbolAddress(&pwl, g_wlo);
    float* base = (float*)pf;
    const size_t SL = (size_t)NPAD * HID;
    float* h0 = base + 0 * SL;
    float* h1 = base + 1 * SL;
    float* h2 = base + 2 * SL;
    float* h3 = base + 3 * SL;
    float* h4 = base + 4 * SL;
    float* h5 = base + 5 * SL;
    float* fs = base + 6 * SL;
    float* fd = base + 7 * SL;
    int* ib = (int*)pi;
    int* deg     = ib;
    int* row_ptr = deg + NN;
    int* cur     = row_ptr + NN + 1;
    int* csr     = cur + NN;
    __nv_bfloat16* whi = (__nv_bfloat16*)pwh;
    __nv_bfloat16* wlo = (__nv_bfloat16*)pwl;

    float* out = (float*)d_out;
    float* hfin = (out_size >= 2 * Nn * HID) ? (out + (size_t)Nn * HID) : h5;

    cudaFuncSetAttribute(tgemm_kernel<1>, cudaFuncAttributeMaxDynamicSharedMemorySize, TG_DSM);
    cudaFuncSetAttribute(tgemm_kernel<2>, cudaFuncAttributeMaxDynamicSharedMemorySize, TG_DSM);

    dim3 tb(256);
    dim3 tg(512);
    int gE = (E + 255) / 256;
    int gx = (Nn + 127) / 128;
    int gGat = (Nn * 32 + 255) / 256;

    // ---- weight conversion ----
    wconv_kernel<<<(WTOT + 255) / 256, tb>>>(W_init, Wsrc_down, Wdst_down,
                                             Wsrc_mid, Wdst_mid, Wsrc_up, Wdst_up, W_fin,
                                             whi, wlo);

    // ---- CSR build ----
    cudaMemsetAsync(deg, 0, sizeof(int) * Nn);
    hist_kernel<<<gE, tb>>>(dst, deg, E);
    scan_kernel<<<1, 1024>>>(deg, row_ptr, cur, Nn);
    scatter_kernel<<<gE, tb>>>(src, dst, cur, csr, E);

    const int OG_INIT = 0, OG_D0 = 32768, OG_D1 = 65536, OG_MID = 98304,
              OG_U0 = 131072, OG_U1 = 196608, OG_FIN = 262144;

    // ---- init: h0 = gelu([x_t|time_emb] @ W_init + b_init) ----
    tgemm_kernel<1><<<gx, tg, TG_DSM>>>(x_t, time_emb, whi + OG_INIT, wlo + OG_INIT,
                                        b_init, h0, nullptr, Nn, 256, 1);

    // ---- down 0 ----
    tgemm_kernel<2><<<gx, tg, TG_DSM>>>(h0, nullptr, whi + OG_D0, wlo + OG_D0,
                                        nullptr, fs, fd, Nn, 128, 0);
    gat_edge_kernel<<<gGat, tb>>>(fs, fd, attn_down, bout_down, bsrc_down, bdst_down,
                                  row_ptr, csr, h1, Nn);

    // ---- down 1 ----
    tgemm_kernel<2><<<gx, tg, TG_DSM>>>(h1, nullptr, whi + OG_D1, wlo + OG_D1,
                                        nullptr, fs, fd, Nn, 128, 0);
    gat_edge_kernel<<<gGat, tb>>>(fs, fd, attn_down + HID, bout_down + HID,
                                  bsrc_down + HID, bdst_down + HID, row_ptr, csr, h2, Nn);

    // ---- mid ----
    tgemm_kernel<2><<<gx, tg, TG_DSM>>>(h2, nullptr, whi + OG_MID, wlo + OG_MID,
                                        nullptr, fs, fd, Nn, 128, 0);
    gat_edge_kernel<<<gGat, tb>>>(fs, fd, attn_mid, bout_mid, bsrc_mid, bdst_mid,
                                  row_ptr, csr, h3, Nn);

    // ---- up 0: [h3|h1] ----
    tgemm_kernel<2><<<gx, tg, TG_DSM>>>(h3, h1, whi + OG_U0, wlo + OG_U0,
                                        nullptr, fs, fd, Nn, 256, 0);
    gat_edge_kernel<<<gGat, tb>>>(fs, fd, attn_up, bout_up, bsrc_up, bdst_up,
                                  row_ptr, csr, h4, Nn);

    // ---- up 1: [h4|h0] ----
    tgemm_kernel<2><<<gx, tg, TG_DSM>>>(h4, h0, whi + OG_U1, wlo + OG_U1,
                                        nullptr, fs, fd, Nn, 256, 0);
    gat_edge_kernel<<<gGat, tb>>>(fs, fd, attn_up + HID, bout_up + HID,
                                  bsrc_up + HID, bdst_up + HID, row_ptr, csr, hfin, Nn);

    // ---- final: out = hfin @ W_fin + b_fin ----
    tgemm_kernel<1><<<gx, tg, TG_DSM>>>(hfin, nullptr, whi + OG_FIN, wlo + OG_FIN,
                                        b_fin, out, nullptr, Nn, 128, 0);
    if (hfin == h5) {
        cudaMemcpyAsync(out + (size_t)Nn * HID, h5, (size_t)Nn * HID * sizeof(float),
                        cudaMemcpyDeviceToDevice);
    }
}

// round 9
// speedup vs baseline: 1.6960x; 1.0111x over previous
#include <cuda_runtime.h>
#include <cuda_bf16.h>
#include <mma.h>
#include <math.h>
#include <stdint.h>

using namespace nvcuda;

#define NN 50000
#define NPAD 50048
#define EE 800000
#define HID 128

// ---------------- scratch (no allocation allowed) ----------------
__device__ float g_buf[(size_t)8 * NPAD * HID];
__device__ int g_ibuf[NN + (NN + 1) + NN + EE + 64];
#define WTOT 278528
__device__ __align__(16) __nv_bfloat16 g_whi[WTOT];
__device__ __align__(16) __nv_bfloat16 g_wlo[WTOT];

__device__ __forceinline__ float gelu_tanh(float x) {
    float x3 = x * x * x;
    float t = tanhf(0.7978845608028654f * (x + 0.044715f * x3));
    return 0.5f * x * (1.0f + t);
}

__device__ __forceinline__ uint32_t smem_u32(const void* p) {
    uint32_t a;
    asm("{ .reg .u64 t; cvta.to.shared.u64 t, %1; cvt.u32.u64 %0, t; }" : "=r"(a) : "l"(p));
    return a;
}
__device__ __forceinline__ void cp_async16(uint32_t dst, const void* src) {
    asm volatile("cp.async.cg.shared.global [%0], [%1], 16;" :: "r"(dst), "l"(src));
}
#define CP_COMMIT() asm volatile("cp.async.commit_group;" ::: "memory")
#define CP_WAIT0()  asm volatile("cp.async.wait_group 0;" ::: "memory")

// ---------------- CSR build ----------------
__global__ void hist_kernel(const int* __restrict__ dst, int* __restrict__ deg, int E) {
    int e = blockIdx.x * blockDim.x + threadIdx.x;
    if (e < E) atomicAdd(&deg[dst[e]], 1);
}

// per-1024-block partial sums
__global__ void scan_part_kernel(const int* __restrict__ deg, int* __restrict__ part, int n) {
    __shared__ int ws[32];
    const int lane = threadIdx.x & 31, wid = threadIdx.x >> 5;
    int i = blockIdx.x * 1024 + threadIdx.x;
    int v = (i < n) ? deg[i] : 0;
#pragma unroll
    for (int o = 16; o; o >>= 1) v += __shfl_xor_sync(0xffffffffu, v, o);
    if (lane == 0) ws[wid] = v;
    __syncthreads();
    if (wid == 0) {
        int x = ws[lane];
#pragma unroll
        for (int o = 16; o; o >>= 1) x += __shfl_xor_sync(0xffffffffu, x, o);
        if (lane == 0) part[blockIdx.x] = x;
    }
}

// 1-warp exclusive scan over nb <= 64 partials
__global__ void scan_off_kernel(int* __restrict__ part, int nb) {
    int lane = threadIdx.x;
    int v0 = (2 * lane < nb) ? part[2 * lane] : 0;
    int v1 = (2 * lane + 1 < nb) ? part[2 * lane + 1] : 0;
    int sum = v0 + v1;
    int x = sum;
#pragma unroll
    for (int o = 1; o < 32; o <<= 1) {
        int t = __shfl_up_sync(0xffffffffu, x, o);
        if (lane >= o) x += t;
    }
    int excl = x - sum;
    if (2 * lane < nb) part[2 * lane] = excl;
    if (2 * lane + 1 < nb) part[2 * lane + 1] = excl + v0;
}

// per-block inclusive scan + global offset -> row_ptr/cur
__global__ void scan_final_kernel(const int* __restrict__ deg, const int* __restrict__ part,
                                  int* __restrict__ row_ptr, int* __restrict__ cur, int n) {
    __shared__ int wsum[32];
    const int lane = threadIdx.x & 31, wid = threadIdx.x >> 5;
    int i = blockIdx.x * 1024 + threadIdx.x;
    int v = (i < n) ? deg[i] : 0;
    int x = v;
#pragma unroll
    for (int o = 1; o < 32; o <<= 1) {
        int t = __shfl_up_sync(0xffffffffu, x, o);
        if (lane >= o) x += t;
    }
    if (lane == 31) wsum[wid] = x;
    __syncthreads();
    if (wid == 0) {
        int y = wsum[lane];
#pragma unroll
        for (int o = 1; o < 32; o <<= 1) {
            int t = __shfl_up_sync(0xffffffffu, y, o);
            if (lane >= o) y += t;
        }
        wsum[lane] = y;
    }
    __syncthreads();
    int off = part[blockIdx.x] + (wid > 0 ? wsum[wid - 1] : 0);
    if (i < n) {
        row_ptr[i + 1] = off + x;
        cur[i] = off + x - v;
    }
    if (i == 0) row_ptr[0] = 0;
}

__global__ void scatter_kernel(const int* __restrict__ src, const int* __restrict__ dst,
                               int* __restrict__ cur, int* __restrict__ csr_src, int E) {
    int e = blockIdx.x * blockDim.x + threadIdx.x;
    if (e < E) {
        int p = atomicAdd(&cur[dst[e]], 1);
        csr_src[p] = src[e];
    }
}

// ---------------- weight transpose + bf16 split ----------------
__global__ void wconv_kernel(
    const float* __restrict__ Wi,
    const float* __restrict__ Wsd, const float* __restrict__ Wdd,
    const float* __restrict__ Wsm, const float* __restrict__ Wdm,
    const float* __restrict__ Wsu, const float* __restrict__ Wdu,
    const float* __restrict__ Wf,
    __nv_bfloat16* __restrict__ bhi, __nv_bfloat16* __restrict__ blo)
{
    int idx = blockIdx.x * blockDim.x + threadIdx.x;
    if (idx >= WTOT) return;
    int base, K; const float *S, *D2;
    if (idx < 32768)       { base = 0;      K = 256; S = Wi;           D2 = nullptr; }
    else if (idx < 65536)  { base = 32768;  K = 128; S = Wsd;          D2 = Wdd; }
    else if (idx < 98304)  { base = 65536;  K = 128; S = Wsd + 16384;  D2 = Wdd + 16384; }
    else if (idx < 131072) { base = 98304;  K = 128; S = Wsm;          D2 = Wdm; }
    else if (idx < 196608) { base = 131072; K = 256; S = Wsu;          D2 = Wdu; }
    else if (idx < 262144) { base = 196608; K = 256; S = Wsu + 32768;  D2 = Wdu + 32768; }
    else                   { base = 262144; K = 128; S = Wf;           D2 = nullptr; }
    int local = idx - base;
    int n = local / K, k = local - n * K;
    const float* W = (D2 && n >= 128) ? D2 : S;
    int nc = (D2 && n >= 128) ? n - 128 : n;
    float x = W[(size_t)k * 128 + nc];
    __nv_bfloat16 h = __float2bfloat16_rn(x);
    bhi[idx] = h;
    blo[idx] = __float2bfloat16_rn(x - __bfloat162float(h));
}

// ---------------- wmma bf16-split GEMM, cp.async double-buffered -----------
#define STG 61440
#define SAH 0
#define SAL 10240
#define SBH 20480
#define SBL 40960
#define TG_DSM (2 * STG)

template<int NB>
__global__ __launch_bounds__(512) void tgemm_kernel(
    const float* __restrict__ A1, const float* __restrict__ A2,
    const __nv_bfloat16* __restrict__ Bhi, const __nv_bfloat16* __restrict__ Blo,
    const float* __restrict__ bias,
    float* __restrict__ Ca, float* __restrict__ Cb,
    int M, int K, int act)
{
    extern __shared__ char dsm[];
    const uint32_t sb = smem_u32(dsm);
    const int tid = threadIdx.x;
    const int wid = tid >> 5, lane = tid & 31;
    const int rowBase = blockIdx.x * 128;
    const bool direct = (bias == nullptr);

    __shared__ float sBias[128];
    if (!direct && tid < 128) sBias[tid] = bias[tid];

    // A loader: row = tid>>2 (0..127), 8 consecutive k at (tid&3)*8
    const int ar = tid >> 2, ks8 = (tid & 3) << 3;
    const int grow = rowBase + ar;

    float v[8];
    auto loadA = [&](int c) {
        int kg = (c << 5) + ks8;
        if (grow < M) {
            const float* Ap; int kl;
            if (kg < 128) { Ap = A1; kl = kg; } else { Ap = A2; kl = kg - 128; }
            const float4* p = reinterpret_cast<const float4*>(Ap + (size_t)grow * 128 + kl);
            float4 q0 = p[0], q1 = p[1];
            v[0] = q0.x; v[1] = q0.y; v[2] = q0.z; v[3] = q0.w;
            v[4] = q1.x; v[5] = q1.y; v[6] = q1.z; v[7] = q1.w;
        } else {
#pragma unroll
            for (int i = 0; i < 8; i++) v[i] = 0.0f;
        }
    };
    auto storeA = [&](int st) {
        uint32_t hw[4], lw[4];
#pragma unroll
        for (int j = 0; j < 4; j++) {
            float x0 = v[j * 2], x1 = v[j * 2 + 1];
            __nv_bfloat16 h0 = __float2bfloat16_rn(x0);
            __nv_bfloat16 h1 = __float2bfloat16_rn(x1);
            __nv_bfloat16 l0 = __float2bfloat16_rn(x0 - __bfloat162float(h0));
            __nv_bfloat16 l1 = __float2bfloat16_rn(x1 - __bfloat162float(h1));
            hw[j] = (uint32_t)__bfloat16_as_ushort(h0) | ((uint32_t)__bfloat16_as_ushort(h1) << 16);
            lw[j] = (uint32_t)__bfloat16_as_ushort(l0) | ((uint32_t)__bfloat16_as_ushort(l1) << 16);
        }
        char* basep = dsm + st * STG;
        int off = ar * 80 + ks8 * 2;
        *reinterpret_cast<uint4*>(basep + SAH + off) = make_uint4(hw[0], hw[1], hw[2], hw[3]);
        *reinterpret_cast<uint4*>(basep + SAL + off) = make_uint4(lw[0], lw[1], lw[2], lw[3]);
    };
    auto cpB = [&](int st, int c) {
        if (NB == 2) {
            int r = tid >> 1, q0 = (tid & 1) << 1;
#pragma unroll
            for (int dq = 0; dq < 2; dq++) {
                int q = q0 + dq;
                uint32_t d = sb + st * STG + r * 80 + (q << 4);
                cp_async16(d + SBH, Bhi + (size_t)r * K + (c << 5) + (q << 3));
                cp_async16(d + SBL, Blo + (size_t)r * K + (c << 5) + (q << 3));
            }
        } else {
            int r = tid >> 2, q = tid & 3;
            uint32_t d = sb + st * STG + r * 80 + (q << 4);
            cp_async16(d + SBH, Bhi + (size_t)r * K + (c << 5) + (q << 3));
            cp_async16(d + SBL, Blo + (size_t)r * K + (c << 5) + (q << 3));
        }
    };

    // prologue
    loadA(0);
    cpB(0, 0);
    storeA(0);
    CP_COMMIT();
    CP_WAIT0();
    __syncthreads();

    const int nCh = K >> 5;

    if (NB == 2) {
        // warp tile 32 rows x 64 cols in one output half:
        // rowg = wid&3 (rows rowg*32), colh = (wid>>2)&1, hb = wid>>3
        const int rowg = wid & 3;
        const int colh = (wid >> 2) & 1;
        const int hb   = wid >> 3;

        wmma::fragment<wmma::accumulator, 16, 16, 16, float> acc[8];
#pragma unroll
        for (int t = 0; t < 8; t++) wmma::fill_fragment(acc[t], 0.0f);

        for (int c = 0; c < nCh; c++) {
            const int cur = c & 1;
            const bool more = (c + 1 < nCh);
            if (more) {
                loadA(c + 1);
                cpB(cur ^ 1, c + 1);
                CP_COMMIT();
            }
            const __nv_bfloat16* ah_base = reinterpret_cast<const __nv_bfloat16*>(dsm + cur * STG + SAH);
            const __nv_bfloat16* al_base = reinterpret_cast<const __nv_bfloat16*>(dsm + cur * STG + SAL);
            const __nv_bfloat16* bh_base = reinterpret_cast<const __nv_bfloat16*>(dsm + cur * STG + SBH);
            const __nv_bfloat16* bl_base = reinterpret_cast<const __nv_bfloat16*>(dsm + cur * STG + SBL);
#pragma unroll
            for (int ks = 0; ks < 32; ks += 16) {
                wmma::fragment<wmma::matrix_a, 16, 16, 16, __nv_bfloat16, wmma::row_major> ah0, ah1, al0, al1;
                wmma::load_matrix_sync(ah0, ah_base + (rowg * 32) * 40 + ks, 40);
                wmma::load_matrix_sync(ah1, ah_base + (rowg * 32 + 16) * 40 + ks, 40);
                wmma::load_matrix_sync(al0, al_base + (rowg * 32) * 40 + ks, 40);
                wmma::load_matrix_sync(al1, al_base + (rowg * 32 + 16) * 40 + ks, 40);
#pragma unroll
                for (int t = 0; t < 4; t++) {
                    int brow = hb * 128 + colh * 64 + t * 16;
                    wmma::fragment<wmma::matrix_b, 16, 16, 16, __nv_bfloat16, wmma::col_major> bh, bl;
                    wmma::load_matrix_sync(bh, bh_base + brow * 40 + ks, 40);
                    wmma::load_matrix_sync(bl, bl_base + brow * 40 + ks, 40);
                    wmma::mma_sync(acc[t], ah0, bh, acc[t]);
                    wmma::mma_sync(acc[t], ah0, bl, acc[t]);
                    wmma::mma_sync(acc[t], al0, bh, acc[t]);
                    wmma::mma_sync(acc[4 + t], ah1, bh, acc[4 + t]);
                    wmma::mma_sync(acc[4 + t], ah1, bl, acc[4 + t]);
                    wmma::mma_sync(acc[4 + t], al1, bh, acc[4 + t]);
                }
            }
            if (more) {
                storeA(cur ^ 1);
                CP_WAIT0();
                __syncthreads();
            }
        }
        // direct full-tile stores into padded slabs
        float* Cp = hb ? Cb : Ca;
#pragma unroll
        for (int s = 0; s < 2; s++) {
#pragma unroll
            for (int t = 0; t < 4; t++) {
                wmma::store_matrix_sync(
                    Cp + (size_t)(rowBase + rowg * 32 + s * 16) * 128 + colh * 64 + t * 16,
                    acc[s * 4 + t], 128, wmma::mem_row_major);
            }
        }
    } else {
        const int stripe = wid >> 1, colh = wid & 1;
        wmma::fragment<wmma::accumulator, 16, 16, 16, float> acc[4];
#pragma unroll
        for (int t = 0; t < 4; t++) wmma::fill_fragment(acc[t], 0.0f);

        for (int c = 0; c < nCh; c++) {
            const int cur = c & 1;
            const bool more = (c + 1 < nCh);
            if (more) {
                loadA(c + 1);
                cpB(cur ^ 1, c + 1);
                CP_COMMIT();
            }
            const __nv_bfloat16* ah_base = reinterpret_cast<const __nv_bfloat16*>(dsm + cur * STG + SAH);
            const __nv_bfloat16* al_base = reinterpret_cast<const __nv_bfloat16*>(dsm + cur * STG + SAL);
            const __nv_bfloat16* bh_base = reinterpret_cast<const __nv_bfloat16*>(dsm + cur * STG + SBH);
            const __nv_bfloat16* bl_base = reinterpret_cast<const __nv_bfloat16*>(dsm + cur * STG + SBL);
#pragma unroll
            for (int ks = 0; ks < 32; ks += 16) {
                wmma::fragment<wmma::matrix_a, 16, 16, 16, __nv_bfloat16, wmma::row_major> ah, al;
                wmma::load_matrix_sync(ah, ah_base + stripe * 16 * 40 + ks, 40);
                wmma::load_matrix_sync(al, al_base + stripe * 16 * 40 + ks, 40);
#pragma unroll
                for (int t = 0; t < 4; t++) {
                    int brow = colh * 64 + t * 16;
                    wmma::fragment<wmma::matrix_b, 16, 16, 16, __nv_bfloat16, wmma::col_major> bh, bl;
                    wmma::load_matrix_sync(bh, bh_base + brow * 40 + ks, 40);
                    wmma::load_matrix_sync(bl, bl_base + brow * 40 + ks, 40);
                    wmma::mma_sync(acc[t], ah, bh, acc[t]);
                    wmma::mma_sync(acc[t], ah, bl, acc[t]);
                    wmma::mma_sync(acc[t], al, bh, acc[t]);
                }
            }
            if (more) {
                storeA(cur ^ 1);
                CP_WAIT0();
                __syncthreads();
            }
        }

        __syncthreads();   // reuse dsm as epilogue staging
        float* sE = reinterpret_cast<float*>(dsm) + wid * 256;
#pragma unroll
        for (int t = 0; t < 4; t++) {
            int tg = colh * 4 + t;
            wmma::store_matrix_sync(sE, acc[t], 16, wmma::mem_row_major);
            __syncwarp();
#pragma unroll
            for (int i = 0; i < 8; i++) {
                int idx = i * 32 + lane;
                int row = idx >> 4, col = idx & 15;
                int r = rowBase + stripe * 16 + row;
                if (r < M) {
                    float vv = sE[idx] + sBias[tg * 16 + col];
                    if (act) vv = gelu_tanh(vv);
                    Ca[(size_t)r * 128 + tg * 16 + col] = vv;
                }
            }
            __syncwarp();
        }
    }
}

// ---------------- GATv2 edge aggregation (warp per dst node) ----------------
__device__ __forceinline__ float edge_logit(float4 f, float4 fdv, float4 attnv) {
    float4 ev;
    ev.x = f.x + fdv.x; ev.x = (ev.x > 0.f) ? ev.x : 0.2f * ev.x;
    ev.y = f.y + fdv.y; ev.y = (ev.y > 0.f) ? ev.y : 0.2f * ev.y;
    ev.z = f.z + fdv.z; ev.z = (ev.z > 0.f) ? ev.z : 0.2f * ev.z;
    ev.w = f.w + fdv.w; ev.w = (ev.w > 0.f) ? ev.w : 0.2f * ev.w;
    return ev.x * attnv.x + ev.y * attnv.y + ev.z * attnv.z + ev.w * attnv.w;
}

__global__ __launch_bounds__(256) void gat_edge_kernel(
    const float* __restrict__ fs, const float* __restrict__ fd,
    const float* __restrict__ attn, const float* __restrict__ bout,
    const float* __restrict__ bsrc, const float* __restrict__ bdst,
    const int* __restrict__ row_ptr, const int* __restrict__ csr_src,
    float* __restrict__ hout, int n_nodes)
{
    const int warp = (blockIdx.x * blockDim.x + threadIdx.x) >> 5;
    const int lane = threadIdx.x & 31;
    if (warp >= n_nodes) return;

    const int off = lane * 4;
    const size_t nodeBase = (size_t)warp * 128;

    const float4 bsv = *reinterpret_cast<const float4*>(bsrc + off);
    const float4 bdv = *reinterpret_cast<const float4*>(bdst + off);
    float4 fdv = *reinterpret_cast<const float4*>(fd + nodeBase + off);
    fdv.x += bsv.x + bdv.x; fdv.y += bsv.y + bdv.y;
    fdv.z += bsv.z + bdv.z; fdv.w += bsv.w + bdv.w;
    const float4 attnv = *reinterpret_cast<const float4*>(attn + off);

    float s = 0.0f;
    float4 acc = make_float4(0.f, 0.f, 0.f, 0.f);

    int e = row_ptr[warp];
    const int end = row_ptr[warp + 1];

    for (; e + 8 <= end; e += 8) {
        float4 f[8];
        float l[8];
#pragma unroll
        for (int j = 0; j < 8; j++) {
            int ij = csr_src[e + j];
            f[j] = *reinterpret_cast<const float4*>(fs + (size_t)ij * 128 + off);
        }
#pragma unroll
        for (int j = 0; j < 8; j++) l[j] = edge_logit(f[j], fdv, attnv);
#pragma unroll
        for (int j = 0; j < 8; j++) l[j] += __shfl_xor_sync(0xffffffffu, l[j], 1);
#pragma unroll
        for (int j = 0; j < 8; j++) l[j] += __shfl_xor_sync(0xffffffffu, l[j], 2);
#pragma unroll
        for (int j = 0; j < 8; j++) l[j] += __shfl_xor_sync(0xffffffffu, l[j], 4);
#pragma unroll
        for (int j = 0; j < 8; j++) {
            float p = __expf(fminf(l[j], 80.f));
            s += p;
            acc.x = fmaf(p, f[j].x, acc.x);
            acc.y = fmaf(p, f[j].y, acc.y);
            acc.z = fmaf(p, f[j].z, acc.z);
            acc.w = fmaf(p, f[j].w, acc.w);
        }
    }
    for (; e + 4 <= end; e += 4) {
        float4 f[4];
        float l[4];
#pragma unroll
        for (int j = 0; j < 4; j++) {
            int ij = csr_src[e + j];
            f[j] = *reinterpret_cast<const float4*>(fs + (size_t)ij * 128 + off);
        }
#pragma unroll
        for (int j = 0; j < 4; j++) l[j] = edge_logit(f[j], fdv, attnv);
#pragma unroll
        for (int j = 0; j < 4; j++) l[j] += __shfl_xor_sync(0xffffffffu, l[j], 1);
#pragma unroll
        for (int j = 0; j < 4; j++) l[j] += __shfl_xor_sync(0xffffffffu, l[j], 2);
#pragma unroll
        for (int j = 0; j < 4; j++) l[j] += __shfl_xor_sync(0xffffffffu, l[j], 4);
#pragma unroll
        for (int j = 0; j < 4; j++) {
            float p = __expf(fminf(l[j], 80.f));
            s += p;
            acc.x = fmaf(p, f[j].x, acc.x);
            acc.y = fmaf(p, f[j].y, acc.y);
            acc.z = fmaf(p, f[j].z, acc.z);
            acc.w = fmaf(p, f[j].w, acc.w);
        }
    }
    for (; e < end; e++) {
        int i0 = csr_src[e];
        float4 f0 = *reinterpret_cast<const float4*>(fs + (size_t)i0 * 128 + off);
        float l0 = edge_logit(f0, fdv, attnv);
        l0 += __shfl_xor_sync(0xffffffffu, l0, 1);
        l0 += __shfl_xor_sync(0xffffffffu, l0, 2);
        l0 += __shfl_xor_sync(0xffffffffu, l0, 4);
        float p0 = __expf(fminf(l0, 80.f));
        s += p0;
        acc.x = fmaf(p0, f0.x, acc.x);
        acc.y = fmaf(p0, f0.y, acc.y);
        acc.z = fmaf(p0, f0.z, acc.z);
        acc.w = fmaf(p0, f0.w, acc.w);
    }

    const float4 bv = *reinterpret_cast<const float4*>(bout + off);
    float inv = 1.0f / (s + 1e-9f);
    float salpha = s * inv;   // sum(alpha); 0 for zero-degree nodes
    float4 o;
    o.x = gelu_tanh(acc.x * inv + bsv.x * salpha + bv.x);
    o.y = gelu_tanh(acc.y * inv + bsv.y * salpha + bv.y);
    o.z = gelu_tanh(acc.z * inv + bsv.z * salpha + bv.z);
    o.w = gelu_tanh(acc.w * inv + bsv.w * salpha + bv.w);
    *reinterpret_cast<float4*>(hout + nodeBase + off) = o;
}

// ---------------- launch ----------------
extern "C" void kernel_launch(void* const* d_in, const int* in_sizes, int n_in,
                              void* d_out, int out_size) {
    const float* x_t       = (const float*)d_in[0];
    const float* time_emb  = (const float*)d_in[1];
    const int*   src       = (const int*)d_in[2];
    const int*   dst       = (const int*)d_in[3];
    const float* W_init    = (const float*)d_in[4];
    const float* b_init    = (const float*)d_in[5];
    const float* Wsrc_down = (const float*)d_in[6];
    const float* bsrc_down = (const float*)d_in[7];
    const float* Wdst_down = (const float*)d_in[8];
    const float* bdst_down = (const float*)d_in[9];
    const float* attn_down = (const float*)d_in[10];
    const float* bout_down = (const float*)d_in[11];
    const float* Wsrc_mid  = (const float*)d_in[12];
    const float* bsrc_mid  = (const float*)d_in[13];
    const float* Wdst_mid  = (const float*)d_in[14];
    const float* bdst_mid  = (const float*)d_in[15];
    const float* attn_mid  = (const float*)d_in[16];
    const float* bout_mid  = (const float*)d_in[17];
    const float* Wsrc_up   = (const float*)d_in[18];
    const float* bsrc_up   = (const float*)d_in[19];
    const float* Wdst_up   = (const float*)d_in[20];
    const float* bdst_up   = (const float*)d_in[21];
    const float* attn_up   = (const float*)d_in[22];
    const float* bout_up   = (const float*)d_in[23];
    const float* W_fin     = (const float*)d_in[24];
    const float* b_fin     = (const float*)d_in[25];

    const int Nn = in_sizes[0] / HID;
    const int E  = in_sizes[2];

    void* pf; cudaGetSymbolAddress(&pf, g_buf);
    void* pi; cudaGetSymbolAddress(&pi, g_ibuf);
    void* pwh; cudaGetSymbolAddress(&pwh, g_whi);
    void* pwl; cudaGetSymbolAddress(&pwl, g_wlo);
    float* base = (float*)pf;
    const size_t SL = (size_t)NPAD * HID;
    float* h0 = base + 0 * SL;
    float* h1 = base + 1 * SL;
    float* h2 = base + 2 * SL;
    float* h3 = base + 3 * SL;
    float* h4 = base + 4 * SL;
    float* h5 = base + 5 * SL;
    float* fs = base + 6 * SL;
    float* fd = base + 7 * SL;
    int* ib = (int*)pi;
    int* deg     = ib;
    int* row_ptr = deg + NN;
    int* cur     = row_ptr + NN + 1;
    int* csr     = cur + NN;
    int* part    = csr + EE;   // 64 ints
    __nv_bfloat16* whi = (__nv_bfloat16*)pwh;
    __nv_bfloat16* wlo = (__nv_bfloat16*)pwl;

    float* out = (float*)d_out;
    float* hfin = (out_size >= 2 * Nn * HID) ? (out + (size_t)Nn * HID) : h5;

    cudaFuncSetAttribute(tgemm_kernel<1>, cudaFuncAttributeMaxDynamicSharedMemorySize, TG_DSM);
    cudaFuncSetAttribute(tgemm_kernel<2>, cudaFuncAttributeMaxDynamicSharedMemorySize, TG_DSM);

    dim3 tb(256);
    dim3 tg(512);
    int gE = (E + 255) / 256;
    int gx = (Nn + 127) / 128;
    int gGat = (Nn * 32 + 255) / 256;
    int nBlk = (Nn + 1023) / 1024;

    // ---- weight conversion ----
    wconv_kernel<<<(WTOT + 255) / 256, tb>>>(W_init, Wsrc_down, Wdst_down,
                                             Wsrc_mid, Wdst_mid, Wsrc_up, Wdst_up, W_fin,
                                             whi, wlo);

    // ---- CSR build ----
    cudaMemsetAsync(deg, 0, sizeof(int) * Nn);
    hist_kernel<<<gE, tb>>>(dst, deg, E);
    scan_part_kernel<<<nBlk, 1024>>>(deg, part, Nn);
    scan_off_kernel<<<1, 32>>>(part, nBlk);
    scan_final_kernel<<<nBlk, 1024>>>(deg, part, row_ptr, cur, Nn);
    scatter_kernel<<<gE, tb>>>(src, dst, cur, csr, E);

    const int OG_INIT = 0, OG_D0 = 32768, OG_D1 = 65536, OG_MID = 98304,
              OG_U0 = 131072, OG_U1 = 196608, OG_FIN = 262144;

    // ---- init ----
    tgemm_kernel<1><<<gx, tg, TG_DSM>>>(x_t, time_emb, whi + OG_INIT, wlo + OG_INIT,
                                        b_init, h0, nullptr, Nn, 256, 1);

    // ---- down 0 ----
    tgemm_kernel<2><<<gx, tg, TG_DSM>>>(h0, nullptr, whi + OG_D0, wlo + OG_D0,
                                        nullptr, fs, fd, Nn, 128, 0);
    gat_edge_kernel<<<gGat, tb>>>(fs, fd, attn_down, bout_down, bsrc_down, bdst_down,
                                  row_ptr, csr, h1, Nn);

    // ---- down 1 ----
    tgemm_kernel<2><<<gx, tg, TG_DSM>>>(h1, nullptr, whi + OG_D1, wlo + OG_D1,
                                        nullptr, fs, fd, Nn, 128, 0);
    gat_edge_kernel<<<gGat, tb>>>(fs, fd, attn_down + HID, bout_down + HID,
                                  bsrc_down + HID, bdst_down + HID, row_ptr, csr, h2, Nn);

    // ---- mid ----
    tgemm_kernel<2><<<gx, tg, TG_DSM>>>(h2, nullptr, whi + OG_MID, wlo + OG_MID,
                                        nullptr, fs, fd, Nn, 128, 0);
    gat_edge_kernel<<<gGat, tb>>>(fs, fd, attn_mid, bout_mid, bsrc_mid, bdst_mid,
                                  row_ptr, csr, h3, Nn);

    // ---- up 0: [h3|h1] ----
    tgemm_kernel<2><<<gx, tg, TG_DSM>>>(h3, h1, whi + OG_U0, wlo + OG_U0,
                                        nullptr, fs, fd, Nn, 256, 0);
    gat_edge_kernel<<<gGat, tb>>>(fs, fd, attn_up, bout_up, bsrc_up, bdst_up,
                                  row_ptr, csr, h4, Nn);

    // ---- up 1: [h4|h0] ----
    tgemm_kernel<2><<<gx, tg, TG_DSM>>>(h4, h0, whi + OG_U1, wlo + OG_U1,
                                        nullptr, fs, fd, Nn, 256, 0);
    gat_edge_kernel<<<gGat, tb>>>(fs, fd, attn_up + HID, bout_up + HID,
                                  bsrc_up + HID, bdst_up + HID, row_ptr, csr, hfin, Nn);

    // ---- final ----
    tgemm_kernel<1><<<gx, tg, TG_DSM>>>(hfin, nullptr, whi + OG_FIN, wlo + OG_FIN,
                                        b_fin, out, nullptr, Nn, 128, 0);
    if (hfin == h5) {
        cudaMemcpyAsync(out + (size_t)Nn * HID, h5, (size_t)Nn * HID * sizeof(float),
                        cudaMemcpyDeviceToDevice);
    }
}

// round 10
// speedup vs baseline: 1.8400x; 1.0849x over previous
#include <cuda_runtime.h>
#include <cuda_bf16.h>
#include <mma.h>
#include <math.h>
#include <stdint.h>

using namespace nvcuda;

#define NN 50000
#define NPAD 50048
#define EE 800000
#define HID 128

// ---------------- scratch (no allocation allowed) ----------------
// layout: fs (SL floats), fd (SL floats), then 6 bf16 hi/lo pairs (each pair
// occupies SL floats worth of bytes).
__device__ float g_buf[(size_t)8 * NPAD * HID];
__device__ int g_ibuf[NN + (NN + 1) + NN + EE + 64];
#define WTOT 278528
__device__ __align__(16) __nv_bfloat16 g_whi[WTOT];
__device__ __align__(16) __nv_bfloat16 g_wlo[WTOT];

__device__ __forceinline__ float gelu_tanh(float x) {
    float x3 = x * x * x;
    float t = tanhf(0.7978845608028654f * (x + 0.044715f * x3));
    return 0.5f * x * (1.0f + t);
}

__device__ __forceinline__ uint32_t smem_u32(const void* p) {
    uint32_t a;
    asm("{ .reg .u64 t; cvta.to.shared.u64 t, %1; cvt.u32.u64 %0, t; }" : "=r"(a) : "l"(p));
    return a;
}
__device__ __forceinline__ void cp_async16(uint32_t dst, const void* src) {
    asm volatile("cp.async.cg.shared.global [%0], [%1], 16;" :: "r"(dst), "l"(src));
}
#define CP_COMMIT() asm volatile("cp.async.commit_group;" ::: "memory")
#define CP_WAIT0()  asm volatile("cp.async.wait_group 0;" ::: "memory")
#define CP_WAIT1()  asm volatile("cp.async.wait_group 1;" ::: "memory")

// ---------------- CSR build ----------------
__global__ void hist_kernel(const int* __restrict__ dst, int* __restrict__ deg, int E) {
    int e = blockIdx.x * blockDim.x + threadIdx.x;
    if (e < E) atomicAdd(&deg[dst[e]], 1);
}

__global__ void scan_part_kernel(const int* __restrict__ deg, int* __restrict__ part, int n) {
    __shared__ int ws[32];
    const int lane = threadIdx.x & 31, wid = threadIdx.x >> 5;
    int i = blockIdx.x * 1024 + threadIdx.x;
    int v = (i < n) ? deg[i] : 0;
#pragma unroll
    for (int o = 16; o; o >>= 1) v += __shfl_xor_sync(0xffffffffu, v, o);
    if (lane == 0) ws[wid] = v;
    __syncthreads();
    if (wid == 0) {
        int x = ws[lane];
#pragma unroll
        for (int o = 16; o; o >>= 1) x += __shfl_xor_sync(0xffffffffu, x, o);
        if (lane == 0) part[blockIdx.x] = x;
    }
}

__global__ void scan_off_kernel(int* __restrict__ part, int nb) {
    int lane = threadIdx.x;
    int v0 = (2 * lane < nb) ? part[2 * lane] : 0;
    int v1 = (2 * lane + 1 < nb) ? part[2 * lane + 1] : 0;
    int sum = v0 + v1;
    int x = sum;
#pragma unroll
    for (int o = 1; o < 32; o <<= 1) {
        int t = __shfl_up_sync(0xffffffffu, x, o);
        if (lane >= o) x += t;
    }
    int excl = x - sum;
    if (2 * lane < nb) part[2 * lane] = excl;
    if (2 * lane + 1 < nb) part[2 * lane + 1] = excl + v0;
}

__global__ void scan_final_kernel(const int* __restrict__ deg, const int* __restrict__ part,
                                  int* __restrict__ row_ptr, int* __restrict__ cur, int n) {
    __shared__ int wsum[32];
    const int lane = threadIdx.x & 31, wid = threadIdx.x >> 5;
    int i = blockIdx.x * 1024 + threadIdx.x;
    int v = (i < n) ? deg[i] : 0;
    int x = v;
#pragma unroll
    for (int o = 1; o < 32; o <<= 1) {
        int t = __shfl_up_sync(0xffffffffu, x, o);
        if (lane >= o) x += t;
    }
    if (lane == 31) wsum[wid] = x;
    __syncthreads();
    if (wid == 0) {
        int y = wsum[lane];
#pragma unroll
        for (int o = 1; o < 32; o <<= 1) {
            int t = __shfl_up_sync(0xffffffffu, y, o);
            if (lane >= o) y += t;
        }
        wsum[lane] = y;
    }
    __syncthreads();
    int off = part[blockIdx.x] + (wid > 0 ? wsum[wid - 1] : 0);
    if (i < n) {
        row_ptr[i + 1] = off + x;
        cur[i] = off + x - v;
    }
    if (i == 0) row_ptr[0] = 0;
}

__global__ void scatter_kernel(const int* __restrict__ src, const int* __restrict__ dst,
                               int* __restrict__ cur, int* __restrict__ csr_src, int E) {
    int e = blockIdx.x * blockDim.x + threadIdx.x;
    if (e < E) {
        int p = atomicAdd(&cur[dst[e]], 1);
        csr_src[p] = src[e];
    }
}

// ---------------- weight transpose + bf16 split ----------------
__global__ void wconv_kernel(
    const float* __restrict__ Wi,
    const float* __restrict__ Wsd, const float* __restrict__ Wdd,
    const float* __restrict__ Wsm, const float* __restrict__ Wdm,
    const float* __restrict__ Wsu, const float* __restrict__ Wdu,
    const float* __restrict__ Wf,
    __nv_bfloat16* __restrict__ bhi, __nv_bfloat16* __restrict__ blo)
{
    int idx = blockIdx.x * blockDim.x + threadIdx.x;
    if (idx >= WTOT) return;
    int base, K; const float *S, *D2;
    if (idx < 32768)       { base = 0;      K = 256; S = Wi;           D2 = nullptr; }
    else if (idx < 65536)  { base = 32768;  K = 128; S = Wsd;          D2 = Wdd; }
    else if (idx < 98304)  { base = 65536;  K = 128; S = Wsd + 16384;  D2 = Wdd + 16384; }
    else if (idx < 131072) { base = 98304;  K = 128; S = Wsm;          D2 = Wdm; }
    else if (idx < 196608) { base = 131072; K = 256; S = Wsu;          D2 = Wdu; }
    else if (idx < 262144) { base = 196608; K = 256; S = Wsu + 32768;  D2 = Wdu + 32768; }
    else                   { base = 262144; K = 128; S = Wf;           D2 = nullptr; }
    int local = idx - base;
    int n = local / K, k = local - n * K;
    const float* W = (D2 && n >= 128) ? D2 : S;
    int nc = (D2 && n >= 128) ? n - 128 : n;
    float x = W[(size_t)k * 128 + nc];
    __nv_bfloat16 h = __float2bfloat16_rn(x);
    bhi[idx] = h;
    blo[idx] = __float2bfloat16_rn(x - __bfloat162float(h));
}

// ================= tgemm_fast: A already bf16 hi/lo, full cp.async, 3-stage
// Stage layout (bytes): Ahi[128][40]@0, Alo@10240, Bhi[128*NB][40]@20480,
// Blo@40960. STG=61440; 3 stages = 184320.
#define STG 61440
#define SAH 0
#define SAL 10240
#define SBH 20480
#define SBL 40960
#define TGF_DSM (3 * STG)

template<int NB>
__global__ __launch_bounds__(512) void tgemm_fast(
    const __nv_bfloat16* __restrict__ Ahi1, const __nv_bfloat16* __restrict__ Alo1,
    const __nv_bfloat16* __restrict__ Ahi2, const __nv_bfloat16* __restrict__ Alo2,
    const __nv_bfloat16* __restrict__ Bhi, const __nv_bfloat16* __restrict__ Blo,
    const float* __restrict__ bias,
    float* __restrict__ Ca, float* __restrict__ Cb,
    int M, int K)
{
    extern __shared__ char dsm[];
    const uint32_t sb = smem_u32(dsm);
    const int tid = threadIdx.x;
    const int wid = tid >> 5, lane = tid & 31;
    const int rowBase = blockIdx.x * 128;

    __shared__ float sBias[128];
    if (NB == 1 && tid < 128) sBias[tid] = bias[tid];

    auto cpAll = [&](int st, int c) {
        // A: 128 rows x 32 k of hi and lo
        {
            const __nv_bfloat16* Ah = (c < 4) ? Ahi1 : Ahi2;
            const __nv_bfloat16* Al = (c < 4) ? Alo1 : Alo2;
            int cc = c & 3;
            int r = tid >> 2, q = tid & 3;
            size_t so = (size_t)(rowBase + r) * 128 + cc * 32 + q * 8;
            uint32_t d = sb + st * STG + r * 80 + (q << 4);
            cp_async16(d + SAH, Ah + so);
            cp_async16(d + SAL, Al + so);
        }
        // B: 128*NB rows x 32 k
        if (NB == 2) {
            int r = tid >> 1, q0 = (tid & 1) << 1;
#pragma unroll
            for (int dq = 0; dq < 2; dq++) {
                int q = q0 + dq;
                uint32_t d = sb + st * STG + r * 80 + (q << 4);
                cp_async16(d + SBH, Bhi + (size_t)r * K + (c << 5) + (q << 3));
                cp_async16(d + SBL, Blo + (size_t)r * K + (c << 5) + (q << 3));
            }
        } else {
            int r = tid >> 2, q = tid & 3;
            uint32_t d = sb + st * STG + r * 80 + (q << 4);
            cp_async16(d + SBH, Bhi + (size_t)r * K + (c << 5) + (q << 3));
            cp_async16(d + SBL, Blo + (size_t)r * K + (c << 5) + (q << 3));
        }
    };

    const int nCh = K >> 5;

    // prologue: 2 chunks in flight
    cpAll(0, 0); CP_COMMIT();
    if (nCh > 1) { cpAll(1, 1); CP_COMMIT(); }

    if (NB == 2) {
        const int rowg = wid & 3;
        const int colh = (wid >> 2) & 1;
        const int hb   = wid >> 3;
        wmma::fragment<wmma::accumulator, 16, 16, 16, float> acc[8];
#pragma unroll
        for (int t = 0; t < 8; t++) wmma::fill_fragment(acc[t], 0.0f);

        for (int c = 0; c < nCh; c++) {
            if (c + 1 == nCh) { CP_WAIT0(); } else { CP_WAIT1(); }
            __syncthreads();
            const int st = c % 3;
            const __nv_bfloat16* ah_base = reinterpret_cast<const __nv_bfloat16*>(dsm + st * STG + SAH);
            const __nv_bfloat16* al_base = reinterpret_cast<const __nv_bfloat16*>(dsm + st * STG + SAL);
            const __nv_bfloat16* bh_base = reinterpret_cast<const __nv_bfloat16*>(dsm + st * STG + SBH);
            const __nv_bfloat16* bl_base = reinterpret_cast<const __nv_bfloat16*>(dsm + st * STG + SBL);
#pragma unroll
            for (int ks = 0; ks < 32; ks += 16) {
                wmma::fragment<wmma::matrix_a, 16, 16, 16, __nv_bfloat16, wmma::row_major> ah0, ah1, al0, al1;
                wmma::load_matrix_sync(ah0, ah_base + (rowg * 32) * 40 + ks, 40);
                wmma::load_matrix_sync(ah1, ah_base + (rowg * 32 + 16) * 40 + ks, 40);
                wmma::load_matrix_sync(al0, al_base + (rowg * 32) * 40 + ks, 40);
                wmma::load_matrix_sync(al1, al_base + (rowg * 32 + 16) * 40 + ks, 40);
#pragma unroll
                for (int t = 0; t < 4; t++) {
                    int brow = hb * 128 + colh * 64 + t * 16;
                    wmma::fragment<wmma::matrix_b, 16, 16, 16, __nv_bfloat16, wmma::col_major> bh, bl;
                    wmma::load_matrix_sync(bh, bh_base + brow * 40 + ks, 40);
                    wmma::load_matrix_sync(bl, bl_base + brow * 40 + ks, 40);
                    wmma::mma_sync(acc[t], ah0, bh, acc[t]);
                    wmma::mma_sync(acc[t], ah0, bl, acc[t]);
                    wmma::mma_sync(acc[t], al0, bh, acc[t]);
                    wmma::mma_sync(acc[4 + t], ah1, bh, acc[4 + t]);
                    wmma::mma_sync(acc[4 + t], ah1, bl, acc[4 + t]);
                    wmma::mma_sync(acc[4 + t], al1, bh, acc[4 + t]);
                }
            }
            if (c + 2 < nCh) { cpAll((c + 2) % 3, c + 2); CP_COMMIT(); }
        }
        float* Cp = hb ? Cb : Ca;
#pragma unroll
        for (int s = 0; s < 2; s++) {
#pragma unroll
            for (int t = 0; t < 4; t++) {
                wmma::store_matrix_sync(
                    Cp + (size_t)(rowBase + rowg * 32 + s * 16) * 128 + colh * 64 + t * 16,
                    acc[s * 4 + t], 128, wmma::mem_row_major);
            }
        }
    } else {
        const int stripe = wid >> 1, colh = wid & 1;
        wmma::fragment<wmma::accumulator, 16, 16, 16, float> acc[4];
#pragma unroll
        for (int t = 0; t < 4; t++) wmma::fill_fragment(acc[t], 0.0f);

        for (int c = 0; c < nCh; c++) {
            if (c + 1 == nCh) { CP_WAIT0(); } else { CP_WAIT1(); }
            __syncthreads();
            const int st = c % 3;
            const __nv_bfloat16* ah_base = reinterpret_cast<const __nv_bfloat16*>(dsm + st * STG + SAH);
            const __nv_bfloat16* al_base = reinterpret_cast<const __nv_bfloat16*>(dsm + st * STG + SAL);
            const __nv_bfloat16* bh_base = reinterpret_cast<const __nv_bfloat16*>(dsm + st * STG + SBH);
            const __nv_bfloat16* bl_base = reinterpret_cast<const __nv_bfloat16*>(dsm + st * STG + SBL);
#pragma unroll
            for (int ks = 0; ks < 32; ks += 16) {
                wmma::fragment<wmma::matrix_a, 16, 16, 16, __nv_bfloat16, wmma::row_major> ah, al;
                wmma::load_matrix_sync(ah, ah_base + stripe * 16 * 40 + ks, 40);
                wmma::load_matrix_sync(al, al_base + stripe * 16 * 40 + ks, 40);
#pragma unroll
                for (int t = 0; t < 4; t++) {
                    int brow = colh * 64 + t * 16;
                    wmma::fragment<wmma::matrix_b, 16, 16, 16, __nv_bfloat16, wmma::col_major> bh, bl;
                    wmma::load_matrix_sync(bh, bh_base + brow * 40 + ks, 40);
                    wmma::load_matrix_sync(bl, bl_base + brow * 40 + ks, 40);
                    wmma::mma_sync(acc[t], ah, bh, acc[t]);
                    wmma::mma_sync(acc[t], ah, bl, acc[t]);
                    wmma::mma_sync(acc[t], al, bh, acc[t]);
                }
            }
            if (c + 2 < nCh) { cpAll((c + 2) % 3, c + 2); CP_COMMIT(); }
        }

        __syncthreads();
        float* sE = reinterpret_cast<float*>(dsm) + wid * 256;
#pragma unroll
        for (int t = 0; t < 4; t++) {
            int tg = colh * 4 + t;
            wmma::store_matrix_sync(sE, acc[t], 16, wmma::mem_row_major);
            __syncwarp();
#pragma unroll
            for (int i = 0; i < 8; i++) {
                int idx = i * 32 + lane;
                int row = idx >> 4, col = idx & 15;
                int r = rowBase + stripe * 16 + row;
                if (r < M) {
                    float vv = sE[idx] + sBias[tg * 16 + col];
                    Ca[(size_t)r * 128 + tg * 16 + col] = vv;
                }
            }
            __syncwarp();
        }
    }
}

// ================= tgemm_init: A fp32 (x_t | time_emb), out bf16 pair + gelu
#define STGI 40960
#define IAH 0
#define IAL 10240
#define IBH 20480
#define IBL 30720
#define TGI_DSM (2 * STGI)

__global__ __launch_bounds__(512) void tgemm_init(
    const float* __restrict__ A1, const float* __restrict__ A2,
    const __nv_bfloat16* __restrict__ Bhi, const __nv_bfloat16* __restrict__ Blo,
    const float* __restrict__ bias,
    __nv_bfloat16* __restrict__ Chi, __nv_bfloat16* __restrict__ Clo,
    int M)
{
    const int K = 256;
    extern __shared__ char dsm[];
    const uint32_t sb = smem_u32(dsm);
    const int tid = threadIdx.x;
    const int wid = tid >> 5, lane = tid & 31;
    const int rowBase = blockIdx.x * 128;

    __shared__ float sBias[128];
    if (tid < 128) sBias[tid] = bias[tid];

    const int ar = tid >> 2, ks8 = (tid & 3) << 3;
    const int grow = rowBase + ar;

    float v[8];
    auto loadA = [&](int c) {
        int kg = (c << 5) + ks8;
        if (grow < M) {
            const float* Ap; int kl;
            if (kg < 128) { Ap = A1; kl = kg; } else { Ap = A2; kl = kg - 128; }
            const float4* p = reinterpret_cast<const float4*>(Ap + (size_t)grow * 128 + kl);
            float4 q0 = p[0], q1 = p[1];
            v[0] = q0.x; v[1] = q0.y; v[2] = q0.z; v[3] = q0.w;
            v[4] = q1.x; v[5] = q1.y; v[6] = q1.z; v[7] = q1.w;
        } else {
#pragma unroll
            for (int i = 0; i < 8; i++) v[i] = 0.0f;
        }
    };
    auto storeA = [&](int st) {
        uint32_t hw[4], lw[4];
#pragma unroll
        for (int j = 0; j < 4; j++) {
            float x0 = v[j * 2], x1 = v[j * 2 + 1];
            __nv_bfloat16 h0 = __float2bfloat16_rn(x0);
            __nv_bfloat16 h1 = __float2bfloat16_rn(x1);
            __nv_bfloat16 l0 = __float2bfloat16_rn(x0 - __bfloat162float(h0));
            __nv_bfloat16 l1 = __float2bfloat16_rn(x1 - __bfloat162float(h1));
            hw[j] = (uint32_t)__bfloat16_as_ushort(h0) | ((uint32_t)__bfloat16_as_ushort(h1) << 16);
            lw[j] = (uint32_t)__bfloat16_as_ushort(l0) | ((uint32_t)__bfloat16_as_ushort(l1) << 16);
        }
        char* basep = dsm + st * STGI;
        int off = ar * 80 + ks8 * 2;
        *reinterpret_cast<uint4*>(basep + IAH + off) = make_uint4(hw[0], hw[1], hw[2], hw[3]);
        *reinterpret_cast<uint4*>(basep + IAL + off) = make_uint4(lw[0], lw[1], lw[2], lw[3]);
    };
    auto cpB = [&](int st, int c) {
        int r = tid >> 2, q = tid & 3;
        uint32_t d = sb + st * STGI + r * 80 + (q << 4);
        cp_async16(d + IBH, Bhi + (size_t)r * K + (c << 5) + (q << 3));
        cp_async16(d + IBL, Blo + (size_t)r * K + (c << 5) + (q << 3));
    };

    loadA(0);
    cpB(0, 0);
    storeA(0);
    CP_COMMIT();
    CP_WAIT0();
    __syncthreads();

    const int stripe = wid >> 1, colh = wid & 1;
    wmma::fragment<wmma::accumulator, 16, 16, 16, float> acc[4];
#pragma unroll
    for (int t = 0; t < 4; t++) wmma::fill_fragment(acc[t], 0.0f);

    const int nCh = K >> 5;
    for (int c = 0; c < nCh; c++) {
        const int cur = c & 1;
        const bool more = (c + 1 < nCh);
        if (more) {
            loadA(c + 1);
            cpB(cur ^ 1, c + 1);
            CP_COMMIT();
        }
        const __nv_bfloat16* ah_base = reinterpret_cast<const __nv_bfloat16*>(dsm + cur * STGI + IAH);
        const __nv_bfloat16* al_base = reinterpret_cast<const __nv_bfloat16*>(dsm + cur * STGI + IAL);
        const __nv_bfloat16* bh_base = reinterpret_cast<const __nv_bfloat16*>(dsm + cur * STGI + IBH);
        const __nv_bfloat16* bl_base = reinterpret_cast<const __nv_bfloat16*>(dsm + cur * STGI + IBL);
#pragma unroll
        for (int ks = 0; ks < 32; ks += 16) {
            wmma::fragment<wmma::matrix_a, 16, 16, 16, __nv_bfloat16, wmma::row_major> ah, al;
            wmma::load_matrix_sync(ah, ah_base + stripe * 16 * 40 + ks, 40);
            wmma::load_matrix_sync(al, al_base + stripe * 16 * 40 + ks, 40);
#pragma unroll
            for (int t = 0; t < 4; t++) {
                int brow = colh * 64 + t * 16;
                wmma::fragment<wmma::matrix_b, 16, 16, 16, __nv_bfloat16, wmma::col_major> bh, bl;
                wmma::load_matrix_sync(bh, bh_base + brow * 40 + ks, 40);
                wmma::load_matrix_sync(bl, bl_base + brow * 40 + ks, 40);
                wmma::mma_sync(acc[t], ah, bh, acc[t]);
                wmma::mma_sync(acc[t], ah, bl, acc[t]);
                wmma::mma_sync(acc[t], al, bh, acc[t]);
            }
        }
        if (more) {
            storeA(cur ^ 1);
            CP_WAIT0();
            __syncthreads();
        }
    }

    // epilogue: bias + gelu -> bf16 pair (slabs padded, unguarded)
    __syncthreads();
    float* sE = reinterpret_cast<float*>(dsm) + wid * 256;
#pragma unroll
    for (int t = 0; t < 4; t++) {
        int tg = colh * 4 + t;
        wmma::store_matrix_sync(sE, acc[t], 16, wmma::mem_row_major);
        __syncwarp();
#pragma unroll
        for (int i = 0; i < 8; i++) {
            int idx = i * 32 + lane;
            int row = idx >> 4, col = idx & 15;
            int r = rowBase + stripe * 16 + row;
            float vv = gelu_tanh(sE[idx] + sBias[tg * 16 + col]);
            __nv_bfloat16 hh = __float2bfloat16_rn(vv);
            __nv_bfloat16 ll = __float2bfloat16_rn(vv - __bfloat162float(hh));
            size_t o = (size_t)r * 128 + tg * 16 + col;
            Chi[o] = hh;
            Clo[o] = ll;
        }
        __syncwarp();
    }
}

// ---------------- GATv2 edge aggregation (warp per dst node) ----------------
__device__ __forceinline__ float edge_logit(float4 f, float4 fdv, float4 attnv) {
    float4 ev;
    ev.x = f.x + fdv.x; ev.x = (ev.x > 0.f) ? ev.x : 0.2f * ev.x;
    ev.y = f.y + fdv.y; ev.y = (ev.y > 0.f) ? ev.y : 0.2f * ev.y;
    ev.z = f.z + fdv.z; ev.z = (ev.z > 0.f) ? ev.z : 0.2f * ev.z;
    ev.w = f.w + fdv.w; ev.w = (ev.w > 0.f) ? ev.w : 0.2f * ev.w;
    return ev.x * attnv.x + ev.y * attnv.y + ev.z * attnv.z + ev.w * attnv.w;
}

__global__ __launch_bounds__(256) void gat_edge_kernel(
    const float* __restrict__ fs, const float* __restrict__ fd,
    const float* __restrict__ attn, const float* __restrict__ bout,
    const float* __restrict__ bsrc, const float* __restrict__ bdst,
    const int* __restrict__ row_ptr, const int* __restrict__ csr_src,
    __nv_bfloat16* __restrict__ houthi, __nv_bfloat16* __restrict__ houtlo,
    float* __restrict__ houtf, int n_nodes)
{
    const int warp = (blockIdx.x * blockDim.x + threadIdx.x) >> 5;
    const int lane = threadIdx.x & 31;
    if (warp >= n_nodes) return;

    const int off = lane * 4;
    const size_t nodeBase = (size_t)warp * 128;

    const float4 bsv = *reinterpret_cast<const float4*>(bsrc + off);
    const float4 bdv = *reinterpret_cast<const float4*>(bdst + off);
    float4 fdv = *reinterpret_cast<const float4*>(fd + nodeBase + off);
    fdv.x += bsv.x + bdv.x; fdv.y += bsv.y + bdv.y;
    fdv.z += bsv.z + bdv.z; fdv.w += bsv.w + bdv.w;
    const float4 attnv = *reinterpret_cast<const float4*>(attn + off);

    float s = 0.0f;
    float4 acc = make_float4(0.f, 0.f, 0.f, 0.f);

    int e = row_ptr[warp];
    const int end = row_ptr[warp + 1];

    for (; e + 8 <= end; e += 8) {
        float4 f[8];
        float l[8];
#pragma unroll
        for (int j = 0; j < 8; j++) {
            int ij = csr_src[e + j];
            f[j] = *reinterpret_cast<const float4*>(fs + (size_t)ij * 128 + off);
        }
#pragma unroll
        for (int j = 0; j < 8; j++) l[j] = edge_logit(f[j], fdv, attnv);
#pragma unroll
        for (int j = 0; j < 8; j++) l[j] += __shfl_xor_sync(0xffffffffu, l[j], 1);
#pragma unroll
        for (int j = 0; j < 8; j++) l[j] += __shfl_xor_sync(0xffffffffu, l[j], 2);
#pragma unroll
        for (int j = 0; j < 8; j++) l[j] += __shfl_xor_sync(0xffffffffu, l[j], 4);
#pragma unroll
        for (int j = 0; j < 8; j++) {
            float p = __expf(fminf(l[j], 80.f));
            s += p;
            acc.x = fmaf(p, f[j].x, acc.x);
            acc.y = fmaf(p, f[j].y, acc.y);
            acc.z = fmaf(p, f[j].z, acc.z);
            acc.w = fmaf(p, f[j].w, acc.w);
        }
    }
    for (; e + 4 <= end; e += 4) {
        float4 f[4];
        float l[4];
#pragma unroll
        for (int j = 0; j < 4; j++) {
            int ij = csr_src[e + j];
            f[j] = *reinterpret_cast<const float4*>(fs + (size_t)ij * 128 + off);
        }
#pragma unroll
        for (int j = 0; j < 4; j++) l[j] = edge_logit(f[j], fdv, attnv);
#pragma unroll
        for (int j = 0; j < 4; j++) l[j] += __shfl_xor_sync(0xffffffffu, l[j], 1);
#pragma unroll
        for (int j = 0; j < 4; j++) l[j] += __shfl_xor_sync(0xffffffffu, l[j], 2);
#pragma unroll
        for (int j = 0; j < 4; j++) l[j] += __shfl_xor_sync(0xffffffffu, l[j], 4);
#pragma unroll
        for (int j = 0; j < 4; j++) {
            float p = __expf(fminf(l[j], 80.f));
            s += p;
            acc.x = fmaf(p, f[j].x, acc.x);
            acc.y = fmaf(p, f[j].y, acc.y);
            acc.z = fmaf(p, f[j].z, acc.z);
            acc.w = fmaf(p, f[j].w, acc.w);
        }
    }
    for (; e < end; e++) {
        int i0 = csr_src[e];
        float4 f0 = *reinterpret_cast<const float4*>(fs + (size_t)i0 * 128 + off);
        float l0 = edge_logit(f0, fdv, attnv);
        l0 += __shfl_xor_sync(0xffffffffu, l0, 1);
        l0 += __shfl_xor_sync(0xffffffffu, l0, 2);
        l0 += __shfl_xor_sync(0xffffffffu, l0, 4);
        float p0 = __expf(fminf(l0, 80.f));
        s += p0;
        acc.x = fmaf(p0, f0.x, acc.x);
        acc.y = fmaf(p0, f0.y, acc.y);
        acc.z = fmaf(p0, f0.z, acc.z);
        acc.w = fmaf(p0, f0.w, acc.w);
    }

    const float4 bv = *reinterpret_cast<const float4*>(bout + off);
    float inv = 1.0f / (s + 1e-9f);
    float salpha = s * inv;
    float4 o;
    o.x = gelu_tanh(acc.x * inv + bsv.x * salpha + bv.x);
    o.y = gelu_tanh(acc.y * inv + bsv.y * salpha + bv.y);
    o.z = gelu_tanh(acc.z * inv + bsv.z * salpha + bv.z);
    o.w = gelu_tanh(acc.w * inv + bsv.w * salpha + bv.w);

    // bf16 hi/lo output (for GEMM consumers)
    __nv_bfloat16 h0 = __float2bfloat16_rn(o.x), h1 = __float2bfloat16_rn(o.y);
    __nv_bfloat16 h2 = __float2bfloat16_rn(o.z), h3 = __float2bfloat16_rn(o.w);
    __nv_bfloat16 l0b = __float2bfloat16_rn(o.x - __bfloat162float(h0));
    __nv_bfloat16 l1b = __float2bfloat16_rn(o.y - __bfloat162float(h1));
    __nv_bfloat16 l2b = __float2bfloat16_rn(o.z - __bfloat162float(h2));
    __nv_bfloat16 l3b = __float2bfloat16_rn(o.w - __bfloat162float(h3));
    uint2 hp, lp;
    hp.x = (uint32_t)__bfloat16_as_ushort(h0) | ((uint32_t)__bfloat16_as_ushort(h1) << 16);
    hp.y = (uint32_t)__bfloat16_as_ushort(h2) | ((uint32_t)__bfloat16_as_ushort(h3) << 16);
    lp.x = (uint32_t)__bfloat16_as_ushort(l0b) | ((uint32_t)__bfloat16_as_ushort(l1b) << 16);
    lp.y = (uint32_t)__bfloat16_as_ushort(l2b) | ((uint32_t)__bfloat16_as_ushort(l3b) << 16);
    *reinterpret_cast<uint2*>(houthi + nodeBase + off) = hp;
    *reinterpret_cast<uint2*>(houtlo + nodeBase + off) = lp;
    if (houtf) *reinterpret_cast<float4*>(houtf + nodeBase + off) = o;
}

// ---------------- launch ----------------
extern "C" void kernel_launch(void* const* d_in, const int* in_sizes, int n_in,
                              void* d_out, int out_size) {
    const float* x_t       = (const float*)d_in[0];
    const float* time_emb  = (const float*)d_in[1];
    const int*   src       = (const int*)d_in[2];
    const int*   dst       = (const int*)d_in[3];
    const float* W_init    = (const float*)d_in[4];
    const float* b_init    = (const float*)d_in[5];
    const float* Wsrc_down = (const float*)d_in[6];
    const float* bsrc_down = (const float*)d_in[7];
    const float* Wdst_down = (const float*)d_in[8];
    const float* bdst_down = (const float*)d_in[9];
    const float* attn_down = (const float*)d_in[10];
    const float* bout_down = (const float*)d_in[11];
    const float* Wsrc_mid  = (const float*)d_in[12];
    const float* bsrc_mid  = (const float*)d_in[13];
    const float* Wdst_mid  = (const float*)d_in[14];
    const float* bdst_mid  = (const float*)d_in[15];
    const float* attn_mid  = (const float*)d_in[16];
    const float* bout_mid  = (const float*)d_in[17];
    const float* Wsrc_up   = (const float*)d_in[18];
    const float* bsrc_up   = (const float*)d_in[19];
    const float* Wdst_up   = (const float*)d_in[20];
    const float* bdst_up   = (const float*)d_in[21];
    const float* attn_up   = (const float*)d_in[22];
    const float* bout_up   = (const float*)d_in[23];
    const float* W_fin     = (const float*)d_in[24];
    const float* b_fin     = (const float*)d_in[25];

    const int Nn = in_sizes[0] / HID;
    const int E  = in_sizes[2];

    void* pf; cudaGetSymbolAddress(&pf, g_buf);
    void* pi; cudaGetSymbolAddress(&pi, g_ibuf);
    void* pwh; cudaGetSymbolAddress(&pwh, g_whi);
    void* pwl; cudaGetSymbolAddress(&pwl, g_wlo);
    float* base = (float*)pf;
    const size_t SL = (size_t)NPAD * HID;
    float* fs = base + 0 * SL;
    float* fd = base + 1 * SL;
    __nv_bfloat16* hb = (__nv_bfloat16*)(base + 2 * SL);
    const size_t HS = (size_t)NPAD * HID;
    auto Hhi = [&](int i) { return hb + (size_t)i * 2 * HS; };
    auto Hlo = [&](int i) { return hb + (size_t)i * 2 * HS + HS; };

    int* ib = (int*)pi;
    int* deg     = ib;
    int* row_ptr = deg + NN;
    int* cur     = row_ptr + NN + 1;
    int* csr     = cur + NN;
    int* part    = csr + EE;
    __nv_bfloat16* whi = (__nv_bfloat16*)pwh;
    __nv_bfloat16* wlo = (__nv_bfloat16*)pwl;

    float* out = (float*)d_out;
    float* houtf_fin = (out_size >= 2 * Nn * HID) ? (out + (size_t)Nn * HID) : fd;
    // (fd is free after the last edge kernel only as an output target for fp32 h;
    //  but edge reads fd while writing houtf — must NOT alias. Use fs? also read.
    //  Fall back to no fp32 target + memcpy path never happens since out_size
    //  always fits; keep safe: if it doesn't fit, write into fs-region after? )
    // Safety: when out doesn't fit, use a dedicated region: reuse Hhi(2) pair space
    // (h2 no longer needed at the last layer) as an fp32 buffer.
    float* hf_fallback = (float*)Hhi(2);
    if (out_size < 2 * Nn * HID) houtf_fin = hf_fallback;

    cudaFuncSetAttribute(tgemm_fast<1>, cudaFuncAttributeMaxDynamicSharedMemorySize, TGF_DSM);
    cudaFuncSetAttribute(tgemm_fast<2>, cudaFuncAttributeMaxDynamicSharedMemorySize, TGF_DSM);
    cudaFuncSetAttribute(tgemm_init, cudaFuncAttributeMaxDynamicSharedMemorySize, TGI_DSM);

    dim3 tb(256);
    dim3 tg(512);
    int gE = (E + 255) / 256;
    int gx = (Nn + 127) / 128;
    int gGat = (Nn * 32 + 255) / 256;
    int nBlk = (Nn + 1023) / 1024;

    // ---- weight conversion ----
    wconv_kernel<<<(WTOT + 255) / 256, tb>>>(W_init, Wsrc_down, Wdst_down,
                                             Wsrc_mid, Wdst_mid, Wsrc_up, Wdst_up, W_fin,
                                             whi, wlo);

    // ---- CSR build ----
    cudaMemsetAsync(deg, 0, sizeof(int) * Nn);
    hist_kernel<<<gE, tb>>>(dst, deg, E);
    scan_part_kernel<<<nBlk, 1024>>>(deg, part, Nn);
    scan_off_kernel<<<1, 32>>>(part, nBlk);
    scan_final_kernel<<<nBlk, 1024>>>(deg, part, row_ptr, cur, Nn);
    scatter_kernel<<<gE, tb>>>(src, dst, cur, csr, E);

    const int OG_INIT = 0, OG_D0 = 32768, OG_D1 = 65536, OG_MID = 98304,
              OG_U0 = 131072, OG_U1 = 196608, OG_FIN = 262144;

    // ---- init: H0 = gelu([x_t|time_emb] @ W_init + b_init) (bf16 pair) ----
    tgemm_init<<<gx, tg, TGI_DSM>>>(x_t, time_emb, whi + OG_INIT, wlo + OG_INIT,
                                    b_init, Hhi(0), Hlo(0), Nn);

    // ---- down 0: H0 -> fs,fd -> H1 ----
    tgemm_fast<2><<<gx, tg, TGF_DSM>>>(Hhi(0), Hlo(0), nullptr, nullptr,
                                       whi + OG_D0, wlo + OG_D0, nullptr, fs, fd, Nn, 128);
    gat_edge_kernel<<<gGat, tb>>>(fs, fd, attn_down, bout_down, bsrc_down, bdst_down,
                                  row_ptr, csr, Hhi(1), Hlo(1), nullptr, Nn);

    // ---- down 1: H1 -> H2 ----
    tgemm_fast<2><<<gx, tg, TGF_DSM>>>(Hhi(1), Hlo(1), nullptr, nullptr,
                                       whi + OG_D1, wlo + OG_D1, nullptr, fs, fd, Nn, 128);
    gat_edge_kernel<<<gGat, tb>>>(fs, fd, attn_down + HID, bout_down + HID,
                                  bsrc_down + HID, bdst_down + HID, row_ptr, csr,
                                  Hhi(2), Hlo(2), nullptr, Nn);

    // ---- mid: H2 -> H3 ----
    tgemm_fast<2><<<gx, tg, TGF_DSM>>>(Hhi(2), Hlo(2), nullptr, nullptr,
                                       whi + OG_MID, wlo + OG_MID, nullptr, fs, fd, Nn, 128);
    gat_edge_kernel<<<gGat, tb>>>(fs, fd, attn_mid, bout_mid, bsrc_mid, bdst_mid,
                                  row_ptr, csr, Hhi(3), Hlo(3), nullptr, Nn);

    // ---- up 0: [H3|H1] -> H4 ----
    tgemm_fast<2><<<gx, tg, TGF_DSM>>>(Hhi(3), Hlo(3), Hhi(1), Hlo(1),
                                       whi + OG_U0, wlo + OG_U0, nullptr, fs, fd, Nn, 256);
    gat_edge_kernel<<<gGat, tb>>>(fs, fd, attn_up, bout_up, bsrc_up, bdst_up,
                                  row_ptr, csr, Hhi(4), Hlo(4), nullptr, Nn);

    // ---- up 1: [H4|H0] -> H5 (+ fp32 h to output region) ----
    tgemm_fast<2><<<gx, tg, TGF_DSM>>>(Hhi(4), Hlo(4), Hhi(0), Hlo(0),
                                       whi + OG_U1, wlo + OG_U1, nullptr, fs, fd, Nn, 256);
    gat_edge_kernel<<<gGat, tb>>>(fs, fd, attn_up + HID, bout_up + HID,
                                  bsrc_up + HID, bdst_up + HID, row_ptr, csr,
                                  Hhi(5), Hlo(5), houtf_fin, Nn);

    // ---- final: out = H5 @ W_fin + b_fin ----
    tgemm_fast<1><<<gx, tg, TGF_DSM>>>(Hhi(5), Hlo(5), nullptr, nullptr,
                                       whi + OG_FIN, wlo + OG_FIN, b_fin,
                                       out, nullptr, Nn, 128);
    if (houtf_fin != out + (size_t)Nn * HID && out_size >= 2 * Nn * HID) {
        // unreachable, kept for safety
        cudaMemcpyAsync(out + (size_t)Nn * HID, houtf_fin,
                        (size_t)Nn * HID * sizeof(float), cudaMemcpyDeviceToDevice);
    }
}

// round 11
// speedup vs baseline: 1.8838x; 1.0238x over previous
#include <cuda_runtime.h>
#include <cuda_bf16.h>
#include <mma.h>
#include <math.h>
#include <stdint.h>

using namespace nvcuda;

#define NN 50000
#define NPAD 50048
#define EE 800000
#define HID 128

// ---------------- scratch (no allocation allowed) ----------------
__device__ float g_buf[(size_t)8 * NPAD * HID];
__device__ int g_ibuf[NN + (NN + 1) + NN + EE + 64];
#define WTOT 278528
__device__ __align__(16) __nv_bfloat16 g_whi[WTOT];
__device__ __align__(16) __nv_bfloat16 g_wlo[WTOT];

__device__ __forceinline__ float gelu_tanh(float x) {
    float x3 = x * x * x;
    float t = tanhf(0.7978845608028654f * (x + 0.044715f * x3));
    return 0.5f * x * (1.0f + t);
}

__device__ __forceinline__ uint32_t smem_u32(const void* p) {
    uint32_t a;
    asm("{ .reg .u64 t; cvta.to.shared.u64 t, %1; cvt.u32.u64 %0, t; }" : "=r"(a) : "l"(p));
    return a;
}
__device__ __forceinline__ void cp_async16(uint32_t dst, const void* src) {
    asm volatile("cp.async.cg.shared.global [%0], [%1], 16;" :: "r"(dst), "l"(src));
}
#define CP_COMMIT() asm volatile("cp.async.commit_group;" ::: "memory")
#define CP_WAIT0()  asm volatile("cp.async.wait_group 0;" ::: "memory")
#define CP_WAIT1()  asm volatile("cp.async.wait_group 1;" ::: "memory")

// ---------------- CSR build ----------------
__global__ void hist_kernel(const int* __restrict__ dst, int* __restrict__ deg, int E) {
    int e = blockIdx.x * blockDim.x + threadIdx.x;
    if (e < E) atomicAdd(&deg[dst[e]], 1);
}

__global__ void scan_part_kernel(const int* __restrict__ deg, int* __restrict__ part, int n) {
    __shared__ int ws[32];
    const int lane = threadIdx.x & 31, wid = threadIdx.x >> 5;
    int i = blockIdx.x * 1024 + threadIdx.x;
    int v = (i < n) ? deg[i] : 0;
#pragma unroll
    for (int o = 16; o; o >>= 1) v += __shfl_xor_sync(0xffffffffu, v, o);
    if (lane == 0) ws[wid] = v;
    __syncthreads();
    if (wid == 0) {
        int x = ws[lane];
#pragma unroll
        for (int o = 16; o; o >>= 1) x += __shfl_xor_sync(0xffffffffu, x, o);
        if (lane == 0) part[blockIdx.x] = x;
    }
}

__global__ void scan_off_kernel(int* __restrict__ part, int nb) {
    int lane = threadIdx.x;
    int v0 = (2 * lane < nb) ? part[2 * lane] : 0;
    int v1 = (2 * lane + 1 < nb) ? part[2 * lane + 1] : 0;
    int sum = v0 + v1;
    int x = sum;
#pragma unroll
    for (int o = 1; o < 32; o <<= 1) {
        int t = __shfl_up_sync(0xffffffffu, x, o);
        if (lane >= o) x += t;
    }
    int excl = x - sum;
    if (2 * lane < nb) part[2 * lane] = excl;
    if (2 * lane + 1 < nb) part[2 * lane + 1] = excl + v0;
}

__global__ void scan_final_kernel(const int* __restrict__ deg, const int* __restrict__ part,
                                  int* __restrict__ row_ptr, int* __restrict__ cur, int n) {
    __shared__ int wsum[32];
    const int lane = threadIdx.x & 31, wid = threadIdx.x >> 5;
    int i = blockIdx.x * 1024 + threadIdx.x;
    int v = (i < n) ? deg[i] : 0;
    int x = v;
#pragma unroll
    for (int o = 1; o < 32; o <<= 1) {
        int t = __shfl_up_sync(0xffffffffu, x, o);
        if (lane >= o) x += t;
    }
    if (lane == 31) wsum[wid] = x;
    __syncthreads();
    if (wid == 0) {
        int y = wsum[lane];
#pragma unroll
        for (int o = 1; o < 32; o <<= 1) {
            int t = __shfl_up_sync(0xffffffffu, y, o);
            if (lane >= o) y += t;
        }
        wsum[lane] = y;
    }
    __syncthreads();
    int off = part[blockIdx.x] + (wid > 0 ? wsum[wid - 1] : 0);
    if (i < n) {
        row_ptr[i + 1] = off + x;
        cur[i] = off + x - v;
    }
    if (i == 0) row_ptr[0] = 0;
}

__global__ void scatter_kernel(const int* __restrict__ src, const int* __restrict__ dst,
                               int* __restrict__ cur, int* __restrict__ csr_src, int E) {
    int e = blockIdx.x * blockDim.x + threadIdx.x;
    if (e < E) {
        int p = atomicAdd(&cur[dst[e]], 1);
        csr_src[p] = src[e];
    }
}

// ---------------- weight transpose + bf16 split ----------------
__global__ void wconv_kernel(
    const float* __restrict__ Wi,
    const float* __restrict__ Wsd, const float* __restrict__ Wdd,
    const float* __restrict__ Wsm, const float* __restrict__ Wdm,
    const float* __restrict__ Wsu, const float* __restrict__ Wdu,
    const float* __restrict__ Wf,
    __nv_bfloat16* __restrict__ bhi, __nv_bfloat16* __restrict__ blo)
{
    int idx = blockIdx.x * blockDim.x + threadIdx.x;
    if (idx >= WTOT) return;
    int base, K; const float *S, *D2;
    if (idx < 32768)       { base = 0;      K = 256; S = Wi;           D2 = nullptr; }
    else if (idx < 65536)  { base = 32768;  K = 128; S = Wsd;          D2 = Wdd; }
    else if (idx < 98304)  { base = 65536;  K = 128; S = Wsd + 16384;  D2 = Wdd + 16384; }
    else if (idx < 131072) { base = 98304;  K = 128; S = Wsm;          D2 = Wdm; }
    else if (idx < 196608) { base = 131072; K = 256; S = Wsu;          D2 = Wdu; }
    else if (idx < 262144) { base = 196608; K = 256; S = Wsu + 32768;  D2 = Wdu + 32768; }
    else                   { base = 262144; K = 128; S = Wf;           D2 = nullptr; }
    int local = idx - base;
    int n = local / K, k = local - n * K;
    const float* W = (D2 && n >= 128) ? D2 : S;
    int nc = (D2 && n >= 128) ? n - 128 : n;
    float x = W[(size_t)k * 128 + nc];
    __nv_bfloat16 h = __float2bfloat16_rn(x);
    bhi[idx] = h;
    blo[idx] = __float2bfloat16_rn(x - __bfloat162float(h));
}

// ================= tgemm_fast: A already bf16 hi/lo, full cp.async, 3-stage
#define STG 61440
#define SAH 0
#define SAL 10240
#define SBH 20480
#define SBL 40960
#define TGF_DSM (3 * STG)

template<int NB>
__global__ __launch_bounds__(512) void tgemm_fast(
    const __nv_bfloat16* __restrict__ Ahi1, const __nv_bfloat16* __restrict__ Alo1,
    const __nv_bfloat16* __restrict__ Ahi2, const __nv_bfloat16* __restrict__ Alo2,
    const __nv_bfloat16* __restrict__ Bhi, const __nv_bfloat16* __restrict__ Blo,
    const float* __restrict__ bias,
    float* __restrict__ Ca, float* __restrict__ Cb,
    int M, int K)
{
    extern __shared__ char dsm[];
    const uint32_t sb = smem_u32(dsm);
    const int tid = threadIdx.x;
    const int wid = tid >> 5, lane = tid & 31;
    const int rowBase = blockIdx.x * 128;

    __shared__ float sBias[128];
    if (NB == 1 && tid < 128) sBias[tid] = bias[tid];

    auto cpAll = [&](int st, int c) {
        {
            const __nv_bfloat16* Ah = (c < 4) ? Ahi1 : Ahi2;
            const __nv_bfloat16* Al = (c < 4) ? Alo1 : Alo2;
            int cc = c & 3;
            int r = tid >> 2, q = tid & 3;
            size_t so = (size_t)(rowBase + r) * 128 + cc * 32 + q * 8;
            uint32_t d = sb + st * STG + r * 80 + (q << 4);
            cp_async16(d + SAH, Ah + so);
            cp_async16(d + SAL, Al + so);
        }
        if (NB == 2) {
            int r = tid >> 1, q0 = (tid & 1) << 1;
#pragma unroll
            for (int dq = 0; dq < 2; dq++) {
                int q = q0 + dq;
                uint32_t d = sb + st * STG + r * 80 + (q << 4);
                cp_async16(d + SBH, Bhi + (size_t)r * K + (c << 5) + (q << 3));
                cp_async16(d + SBL, Blo + (size_t)r * K + (c << 5) + (q << 3));
            }
        } else {
            int r = tid >> 2, q = tid & 3;
            uint32_t d = sb + st * STG + r * 80 + (q << 4);
            cp_async16(d + SBH, Bhi + (size_t)r * K + (c << 5) + (q << 3));
            cp_async16(d + SBL, Blo + (size_t)r * K + (c << 5) + (q << 3));
        }
    };

    const int nCh = K >> 5;

    cpAll(0, 0); CP_COMMIT();
    if (nCh > 1) { cpAll(1, 1); CP_COMMIT(); }

    if (NB == 2) {
        const int rowg = wid & 3;
        const int colh = (wid >> 2) & 1;
        const int hb   = wid >> 3;
        wmma::fragment<wmma::accumulator, 16, 16, 16, float> acc[8];
#pragma unroll
        for (int t = 0; t < 8; t++) wmma::fill_fragment(acc[t], 0.0f);

        for (int c = 0; c < nCh; c++) {
            if (c + 1 == nCh) { CP_WAIT0(); } else { CP_WAIT1(); }
            __syncthreads();
            const int st = c % 3;
            const __nv_bfloat16* ah_base = reinterpret_cast<const __nv_bfloat16*>(dsm + st * STG + SAH);
            const __nv_bfloat16* al_base = reinterpret_cast<const __nv_bfloat16*>(dsm + st * STG + SAL);
            const __nv_bfloat16* bh_base = reinterpret_cast<const __nv_bfloat16*>(dsm + st * STG + SBH);
            const __nv_bfloat16* bl_base = reinterpret_cast<const __nv_bfloat16*>(dsm + st * STG + SBL);
#pragma unroll
            for (int ks = 0; ks < 32; ks += 16) {
                wmma::fragment<wmma::matrix_a, 16, 16, 16, __nv_bfloat16, wmma::row_major> ah0, ah1, al0, al1;
                wmma::load_matrix_sync(ah0, ah_base + (rowg * 32) * 40 + ks, 40);
                wmma::load_matrix_sync(ah1, ah_base + (rowg * 32 + 16) * 40 + ks, 40);
                wmma::load_matrix_sync(al0, al_base + (rowg * 32) * 40 + ks, 40);
                wmma::load_matrix_sync(al1, al_base + (rowg * 32 + 16) * 40 + ks, 40);
#pragma unroll
                for (int t = 0; t < 4; t++) {
                    int brow = hb * 128 + colh * 64 + t * 16;
                    wmma::fragment<wmma::matrix_b, 16, 16, 16, __nv_bfloat16, wmma::col_major> bh, bl;
                    wmma::load_matrix_sync(bh, bh_base + brow * 40 + ks, 40);
                    wmma::load_matrix_sync(bl, bl_base + brow * 40 + ks, 40);
                    wmma::mma_sync(acc[t], ah0, bh, acc[t]);
                    wmma::mma_sync(acc[t], ah0, bl, acc[t]);
                    wmma::mma_sync(acc[t], al0, bh, acc[t]);
                    wmma::mma_sync(acc[4 + t], ah1, bh, acc[4 + t]);
                    wmma::mma_sync(acc[4 + t], ah1, bl, acc[4 + t]);
                    wmma::mma_sync(acc[4 + t], al1, bh, acc[4 + t]);
                }
            }
            if (c + 2 < nCh) { cpAll((c + 2) % 3, c + 2); CP_COMMIT(); }
        }
        float* Cp = hb ? Cb : Ca;
#pragma unroll
        for (int s = 0; s < 2; s++) {
#pragma unroll
            for (int t = 0; t < 4; t++) {
                wmma::store_matrix_sync(
                    Cp + (size_t)(rowBase + rowg * 32 + s * 16) * 128 + colh * 64 + t * 16,
                    acc[s * 4 + t], 128, wmma::mem_row_major);
            }
        }
    } else {
        const int stripe = wid >> 1, colh = wid & 1;
        wmma::fragment<wmma::accumulator, 16, 16, 16, float> acc[4];
#pragma unroll
        for (int t = 0; t < 4; t++) wmma::fill_fragment(acc[t], 0.0f);

        for (int c = 0; c < nCh; c++) {
            if (c + 1 == nCh) { CP_WAIT0(); } else { CP_WAIT1(); }
            __syncthreads();
            const int st = c % 3;
            const __nv_bfloat16* ah_base = reinterpret_cast<const __nv_bfloat16*>(dsm + st * STG + SAH);
            const __nv_bfloat16* al_base = reinterpret_cast<const __nv_bfloat16*>(dsm + st * STG + SAL);
            const __nv_bfloat16* bh_base = reinterpret_cast<const __nv_bfloat16*>(dsm + st * STG + SBH);
            const __nv_bfloat16* bl_base = reinterpret_cast<const __nv_bfloat16*>(dsm + st * STG + SBL);
#pragma unroll
            for (int ks = 0; ks < 32; ks += 16) {
                wmma::fragment<wmma::matrix_a, 16, 16, 16, __nv_bfloat16, wmma::row_major> ah, al;
                wmma::load_matrix_sync(ah, ah_base + stripe * 16 * 40 + ks, 40);
                wmma::load_matrix_sync(al, al_base + stripe * 16 * 40 + ks, 40);
#pragma unroll
                for (int t = 0; t < 4; t++) {
                    int brow = colh * 64 + t * 16;
                    wmma::fragment<wmma::matrix_b, 16, 16, 16, __nv_bfloat16, wmma::col_major> bh, bl;
                    wmma::load_matrix_sync(bh, bh_base + brow * 40 + ks, 40);
                    wmma::load_matrix_sync(bl, bl_base + brow * 40 + ks, 40);
                    wmma::mma_sync(acc[t], ah, bh, acc[t]);
                    wmma::mma_sync(acc[t], ah, bl, acc[t]);
                    wmma::mma_sync(acc[t], al, bh, acc[t]);
                }
            }
            if (c + 2 < nCh) { cpAll((c + 2) % 3, c + 2); CP_COMMIT(); }
        }

        __syncthreads();
        float* sE = reinterpret_cast<float*>(dsm) + wid * 256;
#pragma unroll
        for (int t = 0; t < 4; t++) {
            int tg = colh * 4 + t;
            wmma::store_matrix_sync(sE, acc[t], 16, wmma::mem_row_major);
            __syncwarp();
#pragma unroll
            for (int i = 0; i < 8; i++) {
                int idx = i * 32 + lane;
                int row = idx >> 4, col = idx & 15;
                int r = rowBase + stripe * 16 + row;
                if (r < M) {
                    float vv = sE[idx] + sBias[tg * 16 + col];
                    Ca[(size_t)r * 128 + tg * 16 + col] = vv;
                }
            }
            __syncwarp();
        }
    }
}

// ================= tgemm_init: A fp32 (x_t | time_emb), out bf16 pair + gelu
#define STGI 40960
#define IAH 0
#define IAL 10240
#define IBH 20480
#define IBL 30720
#define TGI_DSM (2 * STGI)

__global__ __launch_bounds__(512) void tgemm_init(
    const float* __restrict__ A1, const float* __restrict__ A2,
    const __nv_bfloat16* __restrict__ Bhi, const __nv_bfloat16* __restrict__ Blo,
    const float* __restrict__ bias,
    __nv_bfloat16* __restrict__ Chi, __nv_bfloat16* __restrict__ Clo,
    int M)
{
    const int K = 256;
    extern __shared__ char dsm[];
    const uint32_t sb = smem_u32(dsm);
    const int tid = threadIdx.x;
    const int wid = tid >> 5, lane = tid & 31;
    const int rowBase = blockIdx.x * 128;

    __shared__ float sBias[128];
    if (tid < 128) sBias[tid] = bias[tid];

    const int ar = tid >> 2, ks8 = (tid & 3) << 3;
    const int grow = rowBase + ar;

    float v[8];
    auto loadA = [&](int c) {
        int kg = (c << 5) + ks8;
        if (grow < M) {
            const float* Ap; int kl;
            if (kg < 128) { Ap = A1; kl = kg; } else { Ap = A2; kl = kg - 128; }
            const float4* p = reinterpret_cast<const float4*>(Ap + (size_t)grow * 128 + kl);
            float4 q0 = p[0], q1 = p[1];
            v[0] = q0.x; v[1] = q0.y; v[2] = q0.z; v[3] = q0.w;
            v[4] = q1.x; v[5] = q1.y; v[6] = q1.z; v[7] = q1.w;
        } else {
#pragma unroll
            for (int i = 0; i < 8; i++) v[i] = 0.0f;
        }
    };
    auto storeA = [&](int st) {
        uint32_t hw[4], lw[4];
#pragma unroll
        for (int j = 0; j < 4; j++) {
            float x0 = v[j * 2], x1 = v[j * 2 + 1];
            __nv_bfloat16 h0 = __float2bfloat16_rn(x0);
            __nv_bfloat16 h1 = __float2bfloat16_rn(x1);
            __nv_bfloat16 l0 = __float2bfloat16_rn(x0 - __bfloat162float(h0));
            __nv_bfloat16 l1 = __float2bfloat16_rn(x1 - __bfloat162float(h1));
            hw[j] = (uint32_t)__bfloat16_as_ushort(h0) | ((uint32_t)__bfloat16_as_ushort(h1) << 16);
            lw[j] = (uint32_t)__bfloat16_as_ushort(l0) | ((uint32_t)__bfloat16_as_ushort(l1) << 16);
        }
        char* basep = dsm + st * STGI;
        int off = ar * 80 + ks8 * 2;
        *reinterpret_cast<uint4*>(basep + IAH + off) = make_uint4(hw[0], hw[1], hw[2], hw[3]);
        *reinterpret_cast<uint4*>(basep + IAL + off) = make_uint4(lw[0], lw[1], lw[2], lw[3]);
    };
    auto cpB = [&](int st, int c) {
        int r = tid >> 2, q = tid & 3;
        uint32_t d = sb + st * STGI + r * 80 + (q << 4);
        cp_async16(d + IBH, Bhi + (size_t)r * K + (c << 5) + (q << 3));
        cp_async16(d + IBL, Blo + (size_t)r * K + (c << 5) + (q << 3));
    };

    loadA(0);
    cpB(0, 0);
    storeA(0);
    CP_COMMIT();
    CP_WAIT0();
    __syncthreads();

    const int stripe = wid >> 1, colh = wid & 1;
    wmma::fragment<wmma::accumulator, 16, 16, 16, float> acc[4];
#pragma unroll
    for (int t = 0; t < 4; t++) wmma::fill_fragment(acc[t], 0.0f);

    const int nCh = K >> 5;
    for (int c = 0; c < nCh; c++) {
        const int cur = c & 1;
        const bool more = (c + 1 < nCh);
        if (more) {
            loadA(c + 1);
            cpB(cur ^ 1, c + 1);
            CP_COMMIT();
        }
        const __nv_bfloat16* ah_base = reinterpret_cast<const __nv_bfloat16*>(dsm + cur * STGI + IAH);
        const __nv_bfloat16* al_base = reinterpret_cast<const __nv_bfloat16*>(dsm + cur * STGI + IAL);
        const __nv_bfloat16* bh_base = reinterpret_cast<const __nv_bfloat16*>(dsm + cur * STGI + IBH);
        const __nv_bfloat16* bl_base = reinterpret_cast<const __nv_bfloat16*>(dsm + cur * STGI + IBL);
#pragma unroll
        for (int ks = 0; ks < 32; ks += 16) {
            wmma::fragment<wmma::matrix_a, 16, 16, 16, __nv_bfloat16, wmma::row_major> ah, al;
            wmma::load_matrix_sync(ah, ah_base + stripe * 16 * 40 + ks, 40);
            wmma::load_matrix_sync(al, al_base + stripe * 16 * 40 + ks, 40);
#pragma unroll
            for (int t = 0; t < 4; t++) {
                int brow = colh * 64 + t * 16;
                wmma::fragment<wmma::matrix_b, 16, 16, 16, __nv_bfloat16, wmma::col_major> bh, bl;
                wmma::load_matrix_sync(bh, bh_base + brow * 40 + ks, 40);
                wmma::load_matrix_sync(bl, bl_base + brow * 40 + ks, 40);
                wmma::mma_sync(acc[t], ah, bh, acc[t]);
                wmma::mma_sync(acc[t], ah, bl, acc[t]);
                wmma::mma_sync(acc[t], al, bh, acc[t]);
            }
        }
        if (more) {
            storeA(cur ^ 1);
            CP_WAIT0();
            __syncthreads();
        }
    }

    __syncthreads();
    float* sE = reinterpret_cast<float*>(dsm) + wid * 256;
#pragma unroll
    for (int t = 0; t < 4; t++) {
        int tg = colh * 4 + t;
        wmma::store_matrix_sync(sE, acc[t], 16, wmma::mem_row_major);
        __syncwarp();
#pragma unroll
        for (int i = 0; i < 8; i++) {
            int idx = i * 32 + lane;
            int row = idx >> 4, col = idx & 15;
            int r = rowBase + stripe * 16 + row;
            float vv = gelu_tanh(sE[idx] + sBias[tg * 16 + col]);
            __nv_bfloat16 hh = __float2bfloat16_rn(vv);
            __nv_bfloat16 ll = __float2bfloat16_rn(vv - __bfloat162float(hh));
            size_t o = (size_t)r * 128 + tg * 16 + col;
            Chi[o] = hh;
            Clo[o] = ll;
        }
        __syncwarp();
    }
}

// ---------------- GATv2 edge aggregation (warp per dst node) ----------------
__device__ __forceinline__ float edge_logit(float4 f, float4 fdv, float4 attnv) {
    float4 ev;
    ev.x = f.x + fdv.x; ev.x = (ev.x > 0.f) ? ev.x : 0.2f * ev.x;
    ev.y = f.y + fdv.y; ev.y = (ev.y > 0.f) ? ev.y : 0.2f * ev.y;
    ev.z = f.z + fdv.z; ev.z = (ev.z > 0.f) ? ev.z : 0.2f * ev.z;
    ev.w = f.w + fdv.w; ev.w = (ev.w > 0.f) ? ev.w : 0.2f * ev.w;
    return ev.x * attnv.x + ev.y * attnv.y + ev.z * attnv.z + ev.w * attnv.w;
}

__global__ __launch_bounds__(256) void gat_edge_kernel(
    const float* __restrict__ fs, const float* __restrict__ fd,
    const float* __restrict__ attn, const float* __restrict__ bout,
    const float* __restrict__ bsrc, const float* __restrict__ bdst,
    const int* __restrict__ row_ptr, const int* __restrict__ csr_src,
    __nv_bfloat16* __restrict__ houthi, __nv_bfloat16* __restrict__ houtlo,
    float* __restrict__ houtf, int n_nodes)
{
    const int warp = (blockIdx.x * blockDim.x + threadIdx.x) >> 5;
    const int lane = threadIdx.x & 31;
    if (warp >= n_nodes) return;

    const int off = lane * 4;
    const size_t nodeBase = (size_t)warp * 128;

    const float4 bsv = *reinterpret_cast<const float4*>(bsrc + off);
    const float4 bdv = *reinterpret_cast<const float4*>(bdst + off);
    float4 fdv = *reinterpret_cast<const float4*>(fd + nodeBase + off);
    fdv.x += bsv.x + bdv.x; fdv.y += bsv.y + bdv.y;
    fdv.z += bsv.z + bdv.z; fdv.w += bsv.w + bdv.w;
    const float4 attnv = *reinterpret_cast<const float4*>(attn + off);

    float s = 0.0f;
    float4 acc = make_float4(0.f, 0.f, 0.f, 0.f);

    int e = row_ptr[warp];
    const int end = row_ptr[warp + 1];

    for (; e + 8 <= end; e += 8) {
        float4 f[8];
        float l[8];
#pragma unroll
        for (int j = 0; j < 8; j++) {
            int ij = csr_src[e + j];
            f[j] = *reinterpret_cast<const float4*>(fs + (size_t)ij * 128 + off);
        }
#pragma unroll
        for (int j = 0; j < 8; j++) l[j] = edge_logit(f[j], fdv, attnv);
#pragma unroll
        for (int j = 0; j < 8; j++) l[j] += __shfl_xor_sync(0xffffffffu, l[j], 1);
#pragma unroll
        for (int j = 0; j < 8; j++) l[j] += __shfl_xor_sync(0xffffffffu, l[j], 2);
#pragma unroll
        for (int j = 0; j < 8; j++) l[j] += __shfl_xor_sync(0xffffffffu, l[j], 4);
#pragma unroll
        for (int j = 0; j < 8; j++) {
            float p = __expf(fminf(l[j], 80.f));
            s += p;
            acc.x = fmaf(p, f[j].x, acc.x);
            acc.y = fmaf(p, f[j].y, acc.y);
            acc.z = fmaf(p, f[j].z, acc.z);
            acc.w = fmaf(p, f[j].w, acc.w);
        }
    }
    for (; e + 4 <= end; e += 4) {
        float4 f[4];
        float l[4];
#pragma unroll
        for (int j = 0; j < 4; j++) {
            int ij = csr_src[e + j];
            f[j] = *reinterpret_cast<const float4*>(fs + (size_t)ij * 128 + off);
        }
#pragma unroll
        for (int j = 0; j < 4; j++) l[j] = edge_logit(f[j], fdv, attnv);
#pragma unroll
        for (int j = 0; j < 4; j++) l[j] += __shfl_xor_sync(0xffffffffu, l[j], 1);
#pragma unroll
        for (int j = 0; j < 4; j++) l[j] += __shfl_xor_sync(0xffffffffu, l[j], 2);
#pragma unroll
        for (int j = 0; j < 4; j++) l[j] += __shfl_xor_sync(0xffffffffu, l[j], 4);
#pragma unroll
        for (int j = 0; j < 4; j++) {
            float p = __expf(fminf(l[j], 80.f));
            s += p;
            acc.x = fmaf(p, f[j].x, acc.x);
            acc.y = fmaf(p, f[j].y, acc.y);
            acc.z = fmaf(p, f[j].z, acc.z);
            acc.w = fmaf(p, f[j].w, acc.w);
        }
    }
    for (; e < end; e++) {
        int i0 = csr_src[e];
        float4 f0 = *reinterpret_cast<const float4*>(fs + (size_t)i0 * 128 + off);
        float l0 = edge_logit(f0, fdv, attnv);
        l0 += __shfl_xor_sync(0xffffffffu, l0, 1);
        l0 += __shfl_xor_sync(0xffffffffu, l0, 2);
        l0 += __shfl_xor_sync(0xffffffffu, l0, 4);
        float p0 = __expf(fminf(l0, 80.f));
        s += p0;
        acc.x = fmaf(p0, f0.x, acc.x);
        acc.y = fmaf(p0, f0.y, acc.y);
        acc.z = fmaf(p0, f0.z, acc.z);
        acc.w = fmaf(p0, f0.w, acc.w);
    }

    const float4 bv = *reinterpret_cast<const float4*>(bout + off);
    float inv = 1.0f / (s + 1e-9f);
    float salpha = s * inv;
    float4 o;
    o.x = gelu_tanh(acc.x * inv + bsv.x * salpha + bv.x);
    o.y = gelu_tanh(acc.y * inv + bsv.y * salpha + bv.y);
    o.z = gelu_tanh(acc.z * inv + bsv.z * salpha + bv.z);
    o.w = gelu_tanh(acc.w * inv + bsv.w * salpha + bv.w);

    __nv_bfloat16 h0 = __float2bfloat16_rn(o.x), h1 = __float2bfloat16_rn(o.y);
    __nv_bfloat16 h2 = __float2bfloat16_rn(o.z), h3 = __float2bfloat16_rn(o.w);
    __nv_bfloat16 l0b = __float2bfloat16_rn(o.x - __bfloat162float(h0));
    __nv_bfloat16 l1b = __float2bfloat16_rn(o.y - __bfloat162float(h1));
    __nv_bfloat16 l2b = __float2bfloat16_rn(o.z - __bfloat162float(h2));
    __nv_bfloat16 l3b = __float2bfloat16_rn(o.w - __bfloat162float(h3));
    uint2 hp, lp;
    hp.x = (uint32_t)__bfloat16_as_ushort(h0) | ((uint32_t)__bfloat16_as_ushort(h1) << 16);
    hp.y = (uint32_t)__bfloat16_as_ushort(h2) | ((uint32_t)__bfloat16_as_ushort(h3) << 16);
    lp.x = (uint32_t)__bfloat16_as_ushort(l0b) | ((uint32_t)__bfloat16_as_ushort(l1b) << 16);
    lp.y = (uint32_t)__bfloat16_as_ushort(l2b) | ((uint32_t)__bfloat16_as_ushort(l3b) << 16);
    *reinterpret_cast<uint2*>(houthi + nodeBase + off) = hp;
    *reinterpret_cast<uint2*>(houtlo + nodeBase + off) = lp;
    if (houtf) *reinterpret_cast<float4*>(houtf + nodeBase + off) = o;
}

// ---------------- launch ----------------
extern "C" void kernel_launch(void* const* d_in, const int* in_sizes, int n_in,
                              void* d_out, int out_size) {
    const float* x_t       = (const float*)d_in[0];
    const float* time_emb  = (const float*)d_in[1];
    const int*   src       = (const int*)d_in[2];
    const int*   dst       = (const int*)d_in[3];
    const float* W_init    = (const float*)d_in[4];
    const float* b_init    = (const float*)d_in[5];
    const float* Wsrc_down = (const float*)d_in[6];
    const float* bsrc_down = (const float*)d_in[7];
    const float* Wdst_down = (const float*)d_in[8];
    const float* bdst_down = (const float*)d_in[9];
    const float* attn_down = (const float*)d_in[10];
    const float* bout_down = (const float*)d_in[11];
    const float* Wsrc_mid  = (const float*)d_in[12];
    const float* bsrc_mid  = (const float*)d_in[13];
    const float* Wdst_mid  = (const float*)d_in[14];
    const float* bdst_mid  = (const float*)d_in[15];
    const float* attn_mid  = (const float*)d_in[16];
    const float* bout_mid  = (const float*)d_in[17];
    const float* Wsrc_up   = (const float*)d_in[18];
    const float* bsrc_up   = (const float*)d_in[19];
    const float* Wdst_up   = (const float*)d_in[20];
    const float* bdst_up   = (const float*)d_in[21];
    const float* attn_up   = (const float*)d_in[22];
    const float* bout_up   = (const float*)d_in[23];
    const float* W_fin     = (const float*)d_in[24];
    const float* b_fin     = (const float*)d_in[25];

    const int Nn = in_sizes[0] / HID;
    const int E  = in_sizes[2];

    void* pf; cudaGetSymbolAddress(&pf, g_buf);
    void* pi; cudaGetSymbolAddress(&pi, g_ibuf);
    void* pwh; cudaGetSymbolAddress(&pwh, g_whi);
    void* pwl; cudaGetSymbolAddress(&pwl, g_wlo);
    float* base = (float*)pf;
    const size_t SL = (size_t)NPAD * HID;
    float* fs = base + 0 * SL;
    float* fd = base + 1 * SL;
    __nv_bfloat16* hb = (__nv_bfloat16*)(base + 2 * SL);
    const size_t HS = (size_t)NPAD * HID;
    auto Hhi = [&](int i) { return hb + (size_t)i * 2 * HS; };
    auto Hlo = [&](int i) { return hb + (size_t)i * 2 * HS + HS; };

    int* ib = (int*)pi;
    int* deg     = ib;
    int* row_ptr = deg + NN;
    int* cur     = row_ptr + NN + 1;
    int* csr     = cur + NN;
    int* part    = csr + EE;
    __nv_bfloat16* whi = (__nv_bfloat16*)pwh;
    __nv_bfloat16* wlo = (__nv_bfloat16*)pwl;

    float* out = (float*)d_out;
    float* houtf_fin = (out_size >= 2 * Nn * HID) ? (out + (size_t)Nn * HID)
                                                  : (float*)Hhi(2);

    cudaFuncSetAttribute(tgemm_fast<1>, cudaFuncAttributeMaxDynamicSharedMemorySize, TGF_DSM);
    cudaFuncSetAttribute(tgemm_fast<2>, cudaFuncAttributeMaxDynamicSharedMemorySize, TGF_DSM);
    cudaFuncSetAttribute(tgemm_init, cudaFuncAttributeMaxDynamicSharedMemorySize, TGI_DSM);

    dim3 tb(256);
    dim3 tg(512);
    int gE = (E + 255) / 256;
    int gx = (Nn + 127) / 128;
    int gGat = (Nn * 32 + 255) / 256;
    int nBlk = (Nn + 1023) / 1024;

    // ---- capture-safe fork: CSR build runs on a side stream, concurrent with
    // wconv + init GEMM + down0 GEMM on the main stream. Join before edge0.
    // Stream/events are created per call and intentionally not destroyed
    // (kernel_launch is invoked only a handful of times; these are not device
    // memory allocations).
    cudaStream_t sCsr;
    cudaStreamCreateWithFlags(&sCsr, cudaStreamNonBlocking);
    cudaEvent_t evFork, evJoin;
    cudaEventCreateWithFlags(&evFork, cudaEventDisableTiming);
    cudaEventCreateWithFlags(&evJoin, cudaEventDisableTiming);

    cudaEventRecord(evFork, 0);
    cudaStreamWaitEvent(sCsr, evFork, 0);

    // ---- CSR build (side stream) ----
    cudaMemsetAsync(deg, 0, sizeof(int) * Nn, sCsr);
    hist_kernel<<<gE, tb, 0, sCsr>>>(dst, deg, E);
    scan_part_kernel<<<nBlk, 1024, 0, sCsr>>>(deg, part, Nn);
    scan_off_kernel<<<1, 32, 0, sCsr>>>(part, nBlk);
    scan_final_kernel<<<nBlk, 1024, 0, sCsr>>>(deg, part, row_ptr, cur, Nn);
    scatter_kernel<<<gE, tb, 0, sCsr>>>(src, dst, cur, csr, E);
    cudaEventRecord(evJoin, sCsr);

    const int OG_INIT = 0, OG_D0 = 32768, OG_D1 = 65536, OG_MID = 98304,
              OG_U0 = 131072, OG_U1 = 196608, OG_FIN = 262144;

    // ---- main stream: weight conversion + init + down0 GEMM (independent of CSR)
    wconv_kernel<<<(WTOT + 255) / 256, tb>>>(W_init, Wsrc_down, Wdst_down,
                                             Wsrc_mid, Wdst_mid, Wsrc_up, Wdst_up, W_fin,
                                             whi, wlo);

    tgemm_init<<<gx, tg, TGI_DSM>>>(x_t, time_emb, whi + OG_INIT, wlo + OG_INIT,
                                    b_init, Hhi(0), Hlo(0), Nn);

    tgemm_fast<2><<<gx, tg, TGF_DSM>>>(Hhi(0), Hlo(0), nullptr, nullptr,
                                       whi + OG_D0, wlo + OG_D0, nullptr, fs, fd, Nn, 128);

    // ---- join: edge kernels need CSR ----
    cudaStreamWaitEvent(0, evJoin, 0);

    gat_edge_kernel<<<gGat, tb>>>(fs, fd, attn_down, bout_down, bsrc_down, bdst_down,
                                  row_ptr, csr, Hhi(1), Hlo(1), nullptr, Nn);

    tgemm_fast<2><<<gx, tg, TGF_DSM>>>(Hhi(1), Hlo(1), nullptr, nullptr,
                                       whi + OG_D1, wlo + OG_D1, nullptr, fs, fd, Nn, 128);
    gat_edge_kernel<<<gGat, tb>>>(fs, fd, attn_down + HID, bout_down + HID,
                                  bsrc_down + HID, bdst_down + HID, row_ptr, csr,
                                  Hhi(2), Hlo(2), nullptr, Nn);

    tgemm_fast<2><<<gx, tg, TGF_DSM>>>(Hhi(2), Hlo(2), nullptr, nullptr,
                                       whi + OG_MID, wlo + OG_MID, nullptr, fs, fd, Nn, 128);
    gat_edge_kernel<<<gGat, tb>>>(fs, fd, attn_mid, bout_mid, bsrc_mid, bdst_mid,
                                  row_ptr, csr, Hhi(3), Hlo(3), nullptr, Nn);

    tgemm_fast<2><<<gx, tg, TGF_DSM>>>(Hhi(3), Hlo(3), Hhi(1), Hlo(1),
                                       whi + OG_U0, wlo + OG_U0, nullptr, fs, fd, Nn, 256);
    gat_edge_kernel<<<gGat, tb>>>(fs, fd, attn_up, bout_up, bsrc_up, bdst_up,
                                  row_ptr, csr, Hhi(4), Hlo(4), nullptr, Nn);

    tgemm_fast<2><<<gx, tg, TGF_DSM>>>(Hhi(4), Hlo(4), Hhi(0), Hlo(0),
                                       whi + OG_U1, wlo + OG_U1, nullptr, fs, fd, Nn, 256);
    gat_edge_kernel<<<gGat, tb>>>(fs, fd, attn_up + HID, bout_up + HID,
                                  bsrc_up + HID, bdst_up + HID, row_ptr, csr,
                                  Hhi(5), Hlo(5), houtf_fin, Nn);

    tgemm_fast<1><<<gx, tg, TGF_DSM>>>(Hhi(5), Hlo(5), nullptr, nullptr,
                                       whi + OG_FIN, wlo + OG_FIN, b_fin,
                                       out, nullptr, Nn, 128);
    if (houtf_fin != out + (size_t)Nn * HID && out_size >= 2 * Nn * HID) {
        cudaMemcpyAsync(out + (size_t)Nn * HID, houtf_fin,
                        (size_t)Nn * HID * sizeof(float), cudaMemcpyDeviceToDevice);
    }
}